// round 14
// baseline (speedup 1.0000x reference)
#include <cuda_runtime.h>
#include <math.h>
#include <stdint.h>

// Problem constants: N=4096 nodes, H=256, HEADS=4, DH=64, E=262144, fp32.
#define Nn 4096
#define Hh 256
#define NHEADS 4
#define DHd 64
#define Ee 262144
#define QSC (0.125f * 1.4426950408889634f)
#define CSTRIDE 32

// ---------------- scratch (static device globals) ---------------------------
__device__ int      g_degs[Nn * CSTRIDE];
__device__ int      g_curs[Nn * CSTRIDE];
__device__ int      g_rowptr[Nn + 1];
__device__ int      g_col[Ee];
__device__ uint32_t g_hbf[Nn * 128];        // h packed bf16x2
__device__ float    g_rw[Nn];
__device__ float    g_bsum[Hh];
__device__ float    g_acc[4 * NHEADS * Nn]; // attention partial row-sums (4-way)
__device__ float    g_X1[Nn * Hh];          // aggsum partial 0 / attn O-partial 0
__device__ float    g_X2[Nn * Hh];          // X2 / attn O-partial 1
__device__ float    g_agg[Nn * Hh];         // agg / attn O-partial 2
__device__ float    g_q[Nn * Hh];    // aggsum partial 2 -> qkv out (bf16x2)
__device__ float    g_k[Nn * Hh];    // aggsum partial 3 -> qkv out (bf16x2)
__device__ float    g_v[Nn * Hh];    // qkv out (bf16x2)
__device__ float    g_x[Nn * Hh];
__device__ float    g_t[Nn * 2 * Hh]; // aggsum partial 1 / attn O-partial 3 / FFN mid

// ---------------- helpers -----------------------------------------------------
__device__ __forceinline__ uint32_t smem_u32(const void* p) {
    uint32_t a;
    asm("{ .reg .u64 t; cvta.to.shared.u64 t, %1; cvt.u32.u64 %0, t; }"
        : "=r"(a) : "l"(p));
    return a;
}
__device__ __forceinline__ uint32_t f2tf32(float x) {
    uint32_t r;
    asm("cvt.rna.tf32.f32 %0, %1;" : "=r"(r) : "f"(x));
    return r;
}
__device__ __forceinline__ float tf(float x) { return __uint_as_float(f2tf32(x)); }
__device__ __forceinline__ uint32_t bf2(float lo, float hi) {
    uint32_t r;
    asm("cvt.rn.bf16x2.f32 %0, %1, %2;" : "=r"(r) : "f"(hi), "f"(lo));
    return r;
}
__device__ __forceinline__ float ex2(float x) {
    float r;
    asm("ex2.approx.f32 %0, %1;" : "=f"(r) : "f"(x));
    return r;
}
__device__ __forceinline__ float blo(uint32_t u) { return __uint_as_float(u << 16); }
__device__ __forceinline__ float bhi(uint32_t u) { return __uint_as_float(u & 0xffff0000u); }

__device__ __forceinline__ void mma8(float* c, const uint32_t* a, uint32_t b0, uint32_t b1) {
    asm volatile(
        "mma.sync.aligned.m16n8k8.row.col.f32.tf32.tf32.f32 "
        "{%0,%1,%2,%3}, {%4,%5,%6,%7}, {%8,%9}, {%0,%1,%2,%3};"
        : "+f"(c[0]), "+f"(c[1]), "+f"(c[2]), "+f"(c[3])
        : "r"(a[0]), "r"(a[1]), "r"(a[2]), "r"(a[3]), "r"(b0), "r"(b1));
}
__device__ __forceinline__ void mmabf(float* c, const uint32_t* a, uint32_t b0, uint32_t b1) {
    asm volatile(
        "mma.sync.aligned.m16n8k16.row.col.f32.bf16.bf16.f32 "
        "{%0,%1,%2,%3}, {%4,%5,%6,%7}, {%8,%9}, {%0,%1,%2,%3};"
        : "+f"(c[0]), "+f"(c[1]), "+f"(c[2]), "+f"(c[3])
        : "r"(a[0]), "r"(a[1]), "r"(a[2]), "r"(a[3]), "r"(b0), "r"(b1));
}
__device__ __forceinline__ void ldsm4(uint32_t& r0, uint32_t& r1, uint32_t& r2,
                                      uint32_t& r3, uint32_t a) {
    asm volatile("ldmatrix.sync.aligned.m8n8.x4.shared.b16 {%0,%1,%2,%3}, [%4];"
                 : "=r"(r0), "=r"(r1), "=r"(r2), "=r"(r3) : "r"(a));
}
__device__ __forceinline__ void ldsm4t(uint32_t& r0, uint32_t& r1, uint32_t& r2,
                                       uint32_t& r3, uint32_t a) {
    asm volatile("ldmatrix.sync.aligned.m8n8.x4.trans.shared.b16 {%0,%1,%2,%3}, [%4];"
                 : "=r"(r0), "=r"(r1), "=r"(r2), "=r"(r3) : "r"(a));
}
__device__ __forceinline__ float gelu(float v) {
    return 0.5f * v * (1.0f + erff(v * 0.7071067811865476f));
}
#define CP_COMMIT() asm volatile("cp.async.commit_group;" ::: "memory")
#define CP_WAIT(n)  asm volatile("cp.async.wait_group %0;" :: "n"(n) : "memory")
#define CPA16(sm, g) \
    asm volatile("cp.async.cg.shared.global [%0], [%1], 16;" :: "r"(sm), "l"(g) : "memory")

// ---------------- graph preprocessing ---------------------------------------
__global__ void pack_deg_kernel(const float* __restrict__ h, const int* __restrict__ ei) {
    int i = blockIdx.x * blockDim.x + threadIdx.x;
    int row = i >> 7, col = i & 127;
    float2 hv = *(const float2*)(h + (size_t)row * Hh + col * 2);
    g_hbf[i] = bf2(hv.x, hv.y);
    if (i < 65536) {
        int idx[4];
#pragma unroll
        for (int j = 0; j < 4; j++) idx[j] = ei[Ee + i + j * 65536];
#pragma unroll
        for (int j = 0; j < 4; j++) atomicAdd(&g_degs[idx[j] * CSTRIDE], 1);
    }
}
__global__ void prefix_kernel(const float* __restrict__ bsrc, const float* __restrict__ btgt) {
    __shared__ int sm[1024];
    int t = threadIdx.x;
    if (t < Hh) g_bsum[t] = bsrc[t] + btgt[t];
    int b = t * 4;
    int d0 = g_degs[(b + 0) * CSTRIDE];
    int d1 = g_degs[(b + 1) * CSTRIDE];
    int d2 = g_degs[(b + 2) * CSTRIDE];
    int d3 = g_degs[(b + 3) * CSTRIDE];
    g_degs[(b + 0) * CSTRIDE] = 0;
    g_degs[(b + 1) * CSTRIDE] = 0;
    g_degs[(b + 2) * CSTRIDE] = 0;
    g_degs[(b + 3) * CSTRIDE] = 0;
    int tot = d0 + d1 + d2 + d3;
    sm[t] = tot;
    __syncthreads();
    for (int off = 1; off < 1024; off <<= 1) {
        int v = 0;
        if (t >= off) v = sm[t - off];
        __syncthreads();
        if (t >= off) sm[t] += v;
        __syncthreads();
    }
    int excl = sm[t] - tot;
    g_rowptr[b]     = excl; g_curs[(b + 0) * CSTRIDE] = excl; excl += d0;
    g_rowptr[b + 1] = excl; g_curs[(b + 1) * CSTRIDE] = excl; excl += d1;
    g_rowptr[b + 2] = excl; g_curs[(b + 2) * CSTRIDE] = excl; excl += d2;
    g_rowptr[b + 3] = excl; g_curs[(b + 3) * CSTRIDE] = excl; excl += d3;
    if (t == 1023) g_rowptr[Nn] = excl;
}
__global__ void fill_kernel(const int* __restrict__ ei) {
    int t = blockIdx.x * blockDim.x + threadIdx.x;
    int dst[4], src[4], pos[4];
#pragma unroll
    for (int i = 0; i < 4; i++) {
        dst[i] = ei[Ee + t + i * 65536];
        src[i] = ei[t + i * 65536];
    }
#pragma unroll
    for (int i = 0; i < 4; i++) pos[i] = atomicAdd(&g_curs[dst[i] * CSTRIDE], 1);
#pragma unroll
    for (int i = 0; i < 4; i++) g_col[pos[i]] = src[i];
}
// 4 warps per node: warp q takes 8-edge chunks with chunk index = q (mod 4);
// warp 3 also takes the <8-edge tail. Partials (pre-scaled by inv) go to
// X1 / t / q / k; combined inside the agg GEMM A-stage.
__global__ void __launch_bounds__(256) aggsum_kernel(const float* __restrict__ h) {
    int wrp = threadIdx.x >> 5;
    int n = blockIdx.x * 2 + (wrp >> 2);
    int qw = wrp & 3;
    int lane = threadIdx.x & 31;
    int s0 = g_rowptr[n], s1 = g_rowptr[n + 1];
    int d = s1 - s0;
    float inv = 1.0f / (float)max(d, 1);
    float rwv = d > 0 ? 1.0f : 0.0f;
    const uint4* hb = (const uint4*)g_hbf;

    float a[8] = {};
    for (int e = s0 + qw * 8; e + 8 <= s1; e += 32) {
        int cc[8];
#pragma unroll
        for (int j = 0; j < 8; j++) cc[j] = g_col[e + j];
        uint4 u[8];
#pragma unroll
        for (int j = 0; j < 8; j++) u[j] = hb[(size_t)cc[j] * 32 + lane];
#pragma unroll
        for (int j = 0; j < 8; j++) {
            a[0] += blo(u[j].x); a[1] += bhi(u[j].x);
            a[2] += blo(u[j].y); a[3] += bhi(u[j].y);
            a[4] += blo(u[j].z); a[5] += bhi(u[j].z);
            a[6] += blo(u[j].w); a[7] += bhi(u[j].w);
        }
    }
    if (qw == 3) {  // tail (d % 8 edges)
        for (int e = s1 - (d & 7); e < s1; e++) {
            uint4 u0 = hb[(size_t)g_col[e] * 32 + lane];
            a[0] += blo(u0.x); a[1] += bhi(u0.x);
            a[2] += blo(u0.y); a[3] += bhi(u0.y);
            a[4] += blo(u0.z); a[5] += bhi(u0.z);
            a[6] += blo(u0.w); a[7] += bhi(u0.w);
        }
    }
    float* parts[4] = {g_X1, g_t, g_q, g_k};
    float* x1 = parts[qw] + (size_t)n * Hh + lane * 8;
    *(float4*)x1       = make_float4(a[0] * inv, a[1] * inv, a[2] * inv, a[3] * inv);
    *(float4*)(x1 + 4) = make_float4(a[4] * inv, a[5] * inv, a[6] * inv, a[7] * inv);
    if (qw == 0) {
        const float* hr = h + (size_t)n * Hh + lane * 8;
        float4 h0 = *(const float4*)hr;
        float4 h1 = *(const float4*)(hr + 4);
        float* x2 = g_X2 + (size_t)n * Hh + lane * 8;
        *(float4*)x2       = make_float4(h0.x * rwv, h0.y * rwv, h0.z * rwv, h0.w * rwv);
        *(float4*)(x2 + 4) = make_float4(h1.x * rwv, h1.y * rwv, h1.z * rwv, h1.w * rwv);
        if (lane == 0) g_rw[n] = rwv;
    }
}

// ---------------- tf32 mma.sync GEMM (fp32 out) --------------------------------
// C = (A [+Ab+Ac+Ad elementwise]) @ B (+ A2@B2) (+ bias[n]*rowScale[m]) ; ACT=1: gelu
template <int ACT>
__global__ void __launch_bounds__(256) mm_gemm(
    const float* __restrict__ A, const float* __restrict__ Ab,
    const float* __restrict__ Ac, const float* __restrict__ Ad,
    const float* __restrict__ B,
    const float* __restrict__ A2, const float* __restrict__ B2,
    const float* __restrict__ bias, const float* __restrict__ rowScale,
    float* __restrict__ C, int K, int Nc)
{
    __shared__ __align__(16) float As[128 * 36];
    __shared__ __align__(16) float Bs[32 * 72];
    int tid = threadIdx.x, wid = tid >> 5, lane = tid & 31;
    int gid = lane >> 2, tg = lane & 3;
    int moff = (wid & 3) * 32, noff = (wid >> 2) * 32;
    int m0 = blockIdx.y * 128, n0 = blockIdx.x * 64;

    float c[2][4][4] = {};
    int steps1 = K / 32;
    int steps = A2 ? 2 * steps1 : steps1;

    float4 ra[4], rb2[4], rc[4], rd[4], rb[2];
    {
#pragma unroll
        for (int i = 0; i < 4; i++) {
            int f = tid + i * 256, m = f >> 3, qq = f & 7;
            size_t off = (size_t)(m0 + m) * K + qq * 4;
            ra[i] = *(const float4*)(A + off);
            if (Ab) {
                rb2[i] = *(const float4*)(Ab + off);
                rc[i]  = *(const float4*)(Ac + off);
                rd[i]  = *(const float4*)(Ad + off);
            }
        }
#pragma unroll
        for (int i = 0; i < 2; i++) {
            int f = tid + i * 256, kk = f >> 4, qq = f & 15;
            rb[i] = *(const float4*)(B + (size_t)kk * Nc + n0 + qq * 4);
        }
    }

    for (int s = 0; s < steps; s++) {
        bool cmb = Ab && (s < steps1);
        __syncthreads();
#pragma unroll
        for (int i = 0; i < 4; i++) {
            int f = tid + i * 256, m = f >> 3, qq = f & 7;
            float4 v = ra[i];
            if (cmb) {
                v.x += rb2[i].x + rc[i].x + rd[i].x;
                v.y += rb2[i].y + rc[i].y + rd[i].y;
                v.z += rb2[i].z + rc[i].z + rd[i].z;
                v.w += rb2[i].w + rc[i].w + rd[i].w;
            }
            *(float4*)&As[m * 36 + qq * 4] =
                make_float4(tf(v.x), tf(v.y), tf(v.z), tf(v.w));
        }
#pragma unroll
        for (int i = 0; i < 2; i++) {
            int f = tid + i * 256, kk = f >> 4, qq = f & 15;
            *(float4*)&Bs[kk * 72 + qq * 4] =
                make_float4(tf(rb[i].x), tf(rb[i].y), tf(rb[i].z), tf(rb[i].w));
        }
        __syncthreads();
        if (s + 1 < steps) {
            int s2 = s + 1;
            const float* Ag = (s2 < steps1) ? A : A2;
            const float* Bg = (s2 < steps1) ? B : B2;
            int k0 = ((s2 < steps1) ? s2 : (s2 - steps1)) * 32;
#pragma unroll
            for (int i = 0; i < 4; i++) {
                int f = tid + i * 256, m = f >> 3, qq = f & 7;
                size_t off = (size_t)(m0 + m) * K + k0 + qq * 4;
                ra[i] = *(const float4*)(Ag + off);
                if (Ab && s2 < steps1) {
                    rb2[i] = *(const float4*)(Ab + off);
                    rc[i]  = *(const float4*)(Ac + off);
                    rd[i]  = *(const float4*)(Ad + off);
                }
            }
#pragma unroll
            for (int i = 0; i < 2; i++) {
                int f = tid + i * 256, kk = f >> 4, qq = f & 15;
                rb[i] = *(const float4*)(Bg + (size_t)(k0 + kk) * Nc + n0 + qq * 4);
            }
        }
#pragma unroll
        for (int ks = 0; ks < 4; ks++) {
            int ck = ks * 8 + tg;
            uint32_t a0[4], a1[4];
            a0[0] = __float_as_uint(As[(moff + gid) * 36 + ck]);
            a0[1] = __float_as_uint(As[(moff + gid + 8) * 36 + ck]);
            a0[2] = __float_as_uint(As[(moff + gid) * 36 + ck + 4]);
            a0[3] = __float_as_uint(As[(moff + gid + 8) * 36 + ck + 4]);
            a1[0] = __float_as_uint(As[(moff + 16 + gid) * 36 + ck]);
            a1[1] = __float_as_uint(As[(moff + 24 + gid) * 36 + ck]);
            a1[2] = __float_as_uint(As[(moff + 16 + gid) * 36 + ck + 4]);
            a1[3] = __float_as_uint(As[(moff + 24 + gid) * 36 + ck + 4]);
#pragma unroll
            for (int jn = 0; jn < 4; jn++) {
                uint32_t b0 = __float_as_uint(Bs[ck * 72 + noff + jn * 8 + gid]);
                uint32_t b1 = __float_as_uint(Bs[(ck + 4) * 72 + noff + jn * 8 + gid]);
                mma8(c[0][jn], a0, b0, b1);
                mma8(c[1][jn], a1, b0, b1);
            }
        }
    }

#pragma unroll
    for (int im = 0; im < 2; im++) {
        int r1 = m0 + moff + im * 16 + gid, r2 = r1 + 8;
        float rs1 = rowScale ? rowScale[r1] : 1.0f;
        float rs2 = rowScale ? rowScale[r2] : 1.0f;
#pragma unroll
        for (int jn = 0; jn < 4; jn++) {
            int col = n0 + noff + jn * 8 + 2 * tg;
            float v00 = c[im][jn][0], v01 = c[im][jn][1];
            float v10 = c[im][jn][2], v11 = c[im][jn][3];
            if (bias) {
                float bb0 = bias[col], bb1 = bias[col + 1];
                v00 += bb0 * rs1; v01 += bb1 * rs1;
                v10 += bb0 * rs2; v11 += bb1 * rs2;
            }
            if (ACT == 1) {
                v00 = gelu(v00); v01 = gelu(v01);
                v10 = gelu(v10); v11 = gelu(v11);
            }
            *(float2*)(C + (size_t)r1 * Nc + col) = make_float2(v00, v01);
            *(float2*)(C + (size_t)r2 * Nc + col) = make_float2(v10, v11);
        }
    }
}

// ---------------- tf32 GEMM with fused residual + layernorm --------------------
// C = LN(res + Acomb@B + bias), Acomb = COMBINE ? (A+A2+A3+A4)*il : A.
template <int KK, int COMBINE>
__global__ void __launch_bounds__(256) mm_gemm_ln(
    const float* __restrict__ A, const float* __restrict__ A2,
    const float* __restrict__ A3, const float* __restrict__ A4,
    const float* __restrict__ B,
    const float* __restrict__ bias, const float* __restrict__ res,
    const float* __restrict__ g, const float* __restrict__ be,
    float* __restrict__ C)
{
    __shared__ __align__(16) float As[32 * 36];
    __shared__ __align__(16) float Bs[32 * 264];
    __shared__ float redS[32 * 4], redQ[32 * 4];
    int tid = threadIdx.x, wid = tid >> 5, lane = tid & 31;
    int gid = lane >> 2, tg = lane & 3;
    int moff = (wid & 1) * 16, noff = (wid >> 1) * 64;
    int m0 = blockIdx.x * 32;
    const int steps = KK / 32;
    int am = tid >> 3, aq = tid & 7;

    float il[4];
    if (COMBINE) {
        int r = m0 + am;
#pragma unroll
        for (int hd = 0; hd < 4; hd++)
            il[hd] = 1.0f / (g_acc[hd * Nn + r] + g_acc[(NHEADS + hd) * Nn + r]
                           + g_acc[(2 * NHEADS + hd) * Nn + r]
                           + g_acc[(3 * NHEADS + hd) * Nn + r]);
    }

    float c[8][4] = {};
    float4 ra, ra2, ra3, ra4, rb[8];
    {
        size_t off = (size_t)(m0 + am) * KK + aq * 4;
        ra = *(const float4*)(A + off);
        if (COMBINE) {
            ra2 = *(const float4*)(A2 + off);
            ra3 = *(const float4*)(A3 + off);
            ra4 = *(const float4*)(A4 + off);
        }
#pragma unroll
        for (int i = 0; i < 8; i++) {
            int f = tid + i * 256, kk = f >> 6, q2 = f & 63;
            rb[i] = *(const float4*)(B + (size_t)kk * Hh + q2 * 4);
        }
    }
    for (int s = 0; s < steps; s++) {
        __syncthreads();
        {
            float4 v = ra;
            if (COMBINE) {
                float sc = il[s >> 1];
                v = make_float4((ra.x + ra2.x + ra3.x + ra4.x) * sc,
                                (ra.y + ra2.y + ra3.y + ra4.y) * sc,
                                (ra.z + ra2.z + ra3.z + ra4.z) * sc,
                                (ra.w + ra2.w + ra3.w + ra4.w) * sc);
            }
            *(float4*)&As[am * 36 + aq * 4] =
                make_float4(tf(v.x), tf(v.y), tf(v.z), tf(v.w));
        }
#pragma unroll
        for (int i = 0; i < 8; i++) {
            int f = tid + i * 256, kk = f >> 6, q2 = f & 63;
            *(float4*)&Bs[kk * 264 + q2 * 4] =
                make_float4(tf(rb[i].x), tf(rb[i].y), tf(rb[i].z), tf(rb[i].w));
        }
        __syncthreads();
        if (s + 1 < steps) {
            int k0 = (s + 1) * 32;
            size_t off = (size_t)(m0 + am) * KK + k0 + aq * 4;
            ra = *(const float4*)(A + off);
            if (COMBINE) {
                ra2 = *(const float4*)(A2 + off);
                ra3 = *(const float4*)(A3 + off);
                ra4 = *(const float4*)(A4 + off);
            }
#pragma unroll
            for (int i = 0; i < 8; i++) {
                int f = tid + i * 256, kk = f >> 6, q2 = f & 63;
                rb[i] = *(const float4*)(B + (size_t)(k0 + kk) * Hh + q2 * 4);
            }
        }
#pragma unroll
        for (int ks = 0; ks < 4; ks++) {
            int ck = ks * 8 + tg;
            uint32_t a0[4];
            a0[0] = __float_as_uint(As[(moff + gid) * 36 + ck]);
            a0[1] = __float_as_uint(As[(moff + gid + 8) * 36 + ck]);
            a0[2] = __float_as_uint(As[(moff + gid) * 36 + ck + 4]);
            a0[3] = __float_as_uint(As[(moff + gid + 8) * 36 + ck + 4]);
#pragma unroll
            for (int jn = 0; jn < 8; jn++) {
                uint32_t b0 = __float_as_uint(Bs[ck * 264 + noff + jn * 8 + gid]);
                uint32_t b1 = __float_as_uint(Bs[(ck + 4) * 264 + noff + jn * 8 + gid]);
                mma8(c[jn], a0, b0, b1);
            }
        }
    }

    int r1 = m0 + moff + gid, r2 = r1 + 8;
    float s1 = 0, q1 = 0, s2 = 0, q2 = 0;
#pragma unroll
    for (int jn = 0; jn < 8; jn++) {
        int col = noff + jn * 8 + 2 * tg;
        float2 rr1 = *(const float2*)(res + (size_t)r1 * Hh + col);
        float2 rr2 = *(const float2*)(res + (size_t)r2 * Hh + col);
        float bb0 = bias[col], bb1 = bias[col + 1];
        c[jn][0] += bb0 + rr1.x; c[jn][1] += bb1 + rr1.y;
        c[jn][2] += bb0 + rr2.x; c[jn][3] += bb1 + rr2.y;
        s1 += c[jn][0] + c[jn][1];
        q1 += c[jn][0] * c[jn][0] + c[jn][1] * c[jn][1];
        s2 += c[jn][2] + c[jn][3];
        q2 += c[jn][2] * c[jn][2] + c[jn][3] * c[jn][3];
    }
    s1 += __shfl_xor_sync(0xffffffffu, s1, 1); s1 += __shfl_xor_sync(0xffffffffu, s1, 2);
    q1 += __shfl_xor_sync(0xffffffffu, q1, 1); q1 += __shfl_xor_sync(0xffffffffu, q1, 2);
    s2 += __shfl_xor_sync(0xffffffffu, s2, 1); s2 += __shfl_xor_sync(0xffffffffu, s2, 2);
    q2 += __shfl_xor_sync(0xffffffffu, q2, 1); q2 += __shfl_xor_sync(0xffffffffu, q2, 2);
    if (tg == 0) {
        int cg = wid >> 1;
        redS[(moff + gid) * 4 + cg] = s1;
        redQ[(moff + gid) * 4 + cg] = q1;
        redS[(moff + gid + 8) * 4 + cg] = s2;
        redQ[(moff + gid + 8) * 4 + cg] = q2;
    }
    __syncthreads();
    int ri1 = (moff + gid) * 4, ri2 = (moff + gid + 8) * 4;
    float su1 = redS[ri1] + redS[ri1 + 1] + redS[ri1 + 2] + redS[ri1 + 3];
    float qu1 = redQ[ri1] + redQ[ri1 + 1] + redQ[ri1 + 2] + redQ[ri1 + 3];
    float su2 = redS[ri2] + redS[ri2 + 1] + redS[ri2 + 2] + redS[ri2 + 3];
    float qu2 = redQ[ri2] + redQ[ri2 + 1] + redQ[ri2 + 2] + redQ[ri2 + 3];
    float mu1 = su1 * (1.0f / Hh), mu2 = su2 * (1.0f / Hh);
    float rstd1 = rsqrtf(qu1 * (1.0f / Hh) - mu1 * mu1 + 1e-5f);
    float rstd2 = rsqrtf(qu2 * (1.0f / Hh) - mu2 * mu2 + 1e-5f);
#pragma unroll
    for (int jn = 0; jn < 8; jn++) {
        int col = noff + jn * 8 + 2 * tg;
        float g0 = g[col], g1v = g[col + 1];
        float e0 = be[col], e1 = be[col + 1];
        *(float2*)(C + (size_t)r1 * Hh + col) = make_float2(
            (c[jn][0] - mu1) * rstd1 * g0 + e0, (c[jn][1] - mu1) * rstd1 * g1v + e1);
        *(float2*)(C + (size_t)r2 * Hh + col) = make_float2(
            (c[jn][2] - mu2) * rstd2 * g0 + e0, (c[jn][3] - mu2) * rstd2 * g1v + e1);
    }
}

// ---------------- fused QKV projection (tf32 mma, bf16x2-packed out) -----------
__global__ void __launch_bounds__(256) qkv_gemm(
    const float* __restrict__ h, const float* __restrict__ agg,
    const float* __restrict__ Wq, const float* __restrict__ Wk,
    const float* __restrict__ Wv,
    const float* __restrict__ bq, const float* __restrict__ bk,
    const float* __restrict__ bv,
    uint32_t* __restrict__ qo, uint32_t* __restrict__ ko, uint32_t* __restrict__ vo)
{
    __shared__ __align__(16) float As[128 * 36];
    __shared__ __align__(16) float Bs[32 * 72];
    int z = blockIdx.z;
    const float* A    = (z == 0) ? h  : agg;
    const float* B    = (z == 0) ? Wq : (z == 1 ? Wk : Wv);
    const float* bias = (z == 0) ? bq : (z == 1 ? bk : bv);
    uint32_t*    C    = (z == 0) ? qo : (z == 1 ? ko : vo);
    float osc = (z == 0) ? QSC : 1.0f;

    int tid = threadIdx.x, wid = tid >> 5, lane = tid & 31;
    int gid = lane >> 2, tg = lane & 3;
    int moff = (wid & 3) * 32, noff = (wid >> 2) * 32;
    int m0 = blockIdx.y * 128, n0 = blockIdx.x * 64;

    float c[2][4][4] = {};
    float4 ra[4], rb[2];
#pragma unroll
    for (int i = 0; i < 4; i++) {
        int f = tid + i * 256, m = f >> 3, qq = f & 7;
        ra[i] = *(const float4*)(A + (size_t)(m0 + m) * Hh + qq * 4);
    }
#pragma unroll
    for (int i = 0; i < 2; i++) {
        int f = tid + i * 256, kk = f >> 4, qq = f & 15;
        rb[i] = *(const float4*)(B + (size_t)kk * Hh + n0 + qq * 4);
    }

#pragma unroll
    for (int s = 0; s < 8; s++) {
        __syncthreads();
#pragma unroll
        for (int i = 0; i < 4; i++) {
            int f = tid + i * 256, m = f >> 3, qq = f & 7;
            *(float4*)&As[m * 36 + qq * 4] =
                make_float4(tf(ra[i].x), tf(ra[i].y), tf(ra[i].z), tf(ra[i].w));
        }
#pragma unroll
        for (int i = 0; i < 2; i++) {
            int f = tid + i * 256, kk = f >> 4, qq = f & 15;
            *(float4*)&Bs[kk * 72 + qq * 4] =
                make_float4(tf(rb[i].x), tf(rb[i].y), tf(rb[i].z), tf(rb[i].w));
        }
        __syncthreads();
        if (s + 1 < 8) {
            int k0 = (s + 1) * 32;
#pragma unroll
            for (int i = 0; i < 4; i++) {
                int f = tid + i * 256, m = f >> 3, qq = f & 7;
                ra[i] = *(const float4*)(A + (size_t)(m0 + m) * Hh + k0 + qq * 4);
            }
#pragma unroll
            for (int i = 0; i < 2; i++) {
                int f = tid + i * 256, kk = f >> 4, qq = f & 15;
                rb[i] = *(const float4*)(B + (size_t)(k0 + kk) * Hh + n0 + qq * 4);
            }
        }
#pragma unroll
        for (int ks = 0; ks < 4; ks++) {
            int ck = ks * 8 + tg;
            uint32_t a0[4], a1[4];
            a0[0] = __float_as_uint(As[(moff + gid) * 36 + ck]);
            a0[1] = __float_as_uint(As[(moff + gid + 8) * 36 + ck]);
            a0[2] = __float_as_uint(As[(moff + gid) * 36 + ck + 4]);
            a0[3] = __float_as_uint(As[(moff + gid + 8) * 36 + ck + 4]);
            a1[0] = __float_as_uint(As[(moff + 16 + gid) * 36 + ck]);
            a1[1] = __float_as_uint(As[(moff + 24 + gid) * 36 + ck]);
            a1[2] = __float_as_uint(As[(moff + 16 + gid) * 36 + ck + 4]);
            a1[3] = __float_as_uint(As[(moff + 24 + gid) * 36 + ck + 4]);
#pragma unroll
            for (int jn = 0; jn < 4; jn++) {
                uint32_t b0 = __float_as_uint(Bs[ck * 72 + noff + jn * 8 + gid]);
                uint32_t b1 = __float_as_uint(Bs[(ck + 4) * 72 + noff + jn * 8 + gid]);
                mma8(c[0][jn], a0, b0, b1);
                mma8(c[1][jn], a1, b0, b1);
            }
        }
    }

#pragma unroll
    for (int im = 0; im < 2; im++) {
        int r1 = m0 + moff + im * 16 + gid, r2 = r1 + 8;
#pragma unroll
        for (int jn = 0; jn < 4; jn++) {
            int col = n0 + noff + jn * 8 + 2 * tg;
            float bb0 = bias[col], bb1 = bias[col + 1];
            C[(size_t)r1 * (Hh / 2) + (col >> 1)] =
                bf2((c[im][jn][0] + bb0) * osc, (c[im][jn][1] + bb1) * osc);
            C[(size_t)r2 * (Hh / 2) + (col >> 1)] =
                bf2((c[im][jn][2] + bb0) * osc, (c[im][jn][3] + bb1) * osc);
        }
    }
}

// ---------------- flash attention (bf16 mma, split-K over 4 quarters) ----------
#define AP 36
#define ATILE (64 * AP)
#define NBUF 4
#define ATT_SMEM (NBUF * 2 * ATILE * 4)
#define NT_Q (Nn / 256)  // 16 tiles per quarter
__device__ __forceinline__ void attn_issue(uint32_t sbase, int buf,
                                           const uint32_t* kbf, const uint32_t* vbf,
                                           int t, int hd, int tid) {
    uint32_t Kb = sbase + (uint32_t)buf * (2 * ATILE * 4);
    uint32_t Vb = Kb + ATILE * 4;
#pragma unroll
    for (int i = 0; i < 2; i++) {
        int f = tid + i * 256, r = f >> 3, ch = f & 7;
        const uint32_t* kg = kbf + (size_t)(t * 64 + r) * 128 + hd * 32 + ch * 4;
        const uint32_t* vg = vbf + (size_t)(t * 64 + r) * 128 + hd * 32 + ch * 4;
        uint32_t so = (uint32_t)(r * AP + ch * 4) * 4u;
        CPA16(Kb + so, kg);
        CPA16(Vb + so, vg);
    }
}

__global__ void __launch_bounds__(256) attn_kernel(
    const uint32_t* __restrict__ qbf, const uint32_t* __restrict__ kbf,
    const uint32_t* __restrict__ vbf,
    float* __restrict__ o0, float* __restrict__ o1,
    float* __restrict__ o2, float* __restrict__ o3)
{
    extern __shared__ __align__(16) uint32_t smt[];
    uint32_t sbase = smem_u32(smt);
    int tid = threadIdx.x, wid = tid >> 5, lane = tid & 31;
    int gid = lane >> 2, tg = lane & 3;
    int l8 = lane >> 3, lr = lane & 7;
    int hd = blockIdx.y;
    int z = blockIdx.z;
    int q0 = blockIdx.x * 128;
    int wrow = wid * 16;
    int t0 = z * NT_Q;

    uint32_t koff = (uint32_t)(((l8 >> 1) * 8 + lr) * AP + (l8 & 1) * 4) * 4u;
    uint32_t voff = (uint32_t)((l8 * 8 + lr) * AP) * 4u;

    uint32_t qa[4][4];
    {
        const uint32_t* q1 = qbf + (size_t)(q0 + wrow + gid) * 128 + hd * 32;
        const uint32_t* q2 = q1 + 8 * 128;
#pragma unroll
        for (int ks = 0; ks < 4; ks++) {
            qa[ks][0] = q1[ks * 8 + tg];
            qa[ks][1] = q2[ks * 8 + tg];
            qa[ks][2] = q1[ks * 8 + tg + 4];
            qa[ks][3] = q2[ks * 8 + tg + 4];
        }
    }

    attn_issue(sbase, 0, kbf, vbf, t0, hd, tid); CP_COMMIT();
    attn_issue(sbase, 1, kbf, vbf, t0 + 1, hd, tid); CP_COMMIT();

    float o[8][4] = {};
    float acc0 = 0.0f, acc1 = 0.0f;

    for (int ti = 0; ti < NT_Q; ti++) {
        if (ti + 2 < NT_Q) {
            attn_issue(sbase, (ti + 2) & (NBUF - 1), kbf, vbf, t0 + ti + 2, hd, tid);
            CP_COMMIT();
            CP_WAIT(2);
        } else if (ti + 1 < NT_Q) {
            CP_WAIT(1);
        } else {
            CP_WAIT(0);
        }
        __syncthreads();
        uint32_t Kb = sbase + (uint32_t)(ti & (NBUF - 1)) * (2 * ATILE * 4);
        uint32_t Vb = Kb + ATILE * 4;

        // S = Q @ K^T
        float s[8][4] = {};
#pragma unroll
        for (int kb = 0; kb < 4; kb++) {
#pragma unroll
            for (int jnp = 0; jnp < 4; jnp++) {
                uint32_t b0, b1, b2, b3;
                uint32_t addr = Kb + koff + (uint32_t)(jnp * 16 * AP + kb * 8) * 4u;
                ldsm4(b0, b1, b2, b3, addr);
                mmabf(s[2 * jnp],     qa[kb], b0, b1);
                mmabf(s[2 * jnp + 1], qa[kb], b2, b3);
            }
        }

        // no-max softmax
        uint32_t pa[4][4];
#pragma unroll
        for (int jn = 0; jn < 8; jn++) {
            s[jn][0] = ex2(s[jn][0]);
            s[jn][1] = ex2(s[jn][1]);
            s[jn][2] = ex2(s[jn][2]);
            s[jn][3] = ex2(s[jn][3]);
            acc0 += s[jn][0] + s[jn][1];
            acc1 += s[jn][2] + s[jn][3];
        }
#pragma unroll
        for (int ks = 0; ks < 4; ks++) {
            pa[ks][0] = bf2(s[2 * ks][0], s[2 * ks][1]);
            pa[ks][1] = bf2(s[2 * ks][2], s[2 * ks][3]);
            pa[ks][2] = bf2(s[2 * ks + 1][0], s[2 * ks + 1][1]);
            pa[ks][3] = bf2(s[2 * ks + 1][2], s[2 * ks + 1][3]);
        }

        // O += P @ V
#pragma unroll
        for (int jn = 0; jn < 8; jn++) {
#pragma unroll
            for (int ksp = 0; ksp < 2; ksp++) {
                uint32_t b0, b1, b2, b3;
                uint32_t addr = Vb + voff + (uint32_t)(ksp * 32 * AP + jn * 4) * 4u;
                ldsm4t(b0, b1, b2, b3, addr);
                mmabf(o[jn], pa[2 * ksp],     b0, b1);
                mmabf(o[jn], pa[2 * ksp + 1], b2, b3);
            }
        }
    }

    // partial epilogue
    acc0 += __shfl_xor_sync(0xffffffffu, acc0, 1);
    acc0 += __shfl_xor_sync(0xffffffffu, acc0, 2);
    acc1 += __shfl_xor_sync(0xffffffffu, acc1, 1);
    acc1 += __shfl_xor_sync(0xffffffffu, acc1, 2);
    float* ods[4] = {o0, o1, o2, o3};
    float* od = ods[z];
    int r1 = q0 + wrow + gid, r2 = r1 + 8;
    if (tg == 0) {
        g_acc[(z * NHEADS + hd) * Nn + r1] = acc0;
        g_acc[(z * NHEADS + hd) * Nn + r2] = acc1;
    }
#pragma unroll
    for (int jn = 0; jn < 8; jn++) {
        int col = hd * DHd + jn * 8 + 2 * tg;
        *(float2*)(od + (size_t)r1 * Hh + col) = make_float2(o[jn][0], o[jn][1]);
        *(float2*)(od + (size_t)r2 * Hh + col) = make_float2(o[jn][2], o[jn][3]);
    }
}

// ---------------- launch ------------------------------------------------------
extern "C" void kernel_launch(void* const* d_in, const int* in_sizes, int n_in,
                              void* d_out, int out_size)
{
    const float* h     = (const float*)d_in[0];
    const int*   ei    = (const int*)d_in[1];
    const float* W_src = (const float*)d_in[2];
    const float* b_src = (const float*)d_in[3];
    const float* W_tgt = (const float*)d_in[4];
    const float* b_tgt = (const float*)d_in[5];
    const float* Wq = (const float*)d_in[6];  const float* bq = (const float*)d_in[7];
    const float* Wk = (const float*)d_in[8];  const float* bk = (const float*)d_in[9];
    const float* Wv = (const float*)d_in[10]; const float* bv = (const float*)d_in[11];
    const float* Wo = (const float*)d_in[12]; const float* bo = (const float*)d_in[13];
    const float* W1 = (const float*)d_in[14]; const float* b1 = (const float*)d_in[15];
    const float* W2 = (const float*)d_in[16]; const float* b2 = (const float*)d_in[17];
    const float* g1 = (const float*)d_in[18]; const float* be1 = (const float*)d_in[19];
    const float* g2 = (const float*)d_in[20]; const float* be2 = (const float*)d_in[21];
    float* out = (float*)d_out;

    float *pX1, *pX2, *pagg, *pq, *pk, *pv, *px, *pt, *pbsum, *prw;
    cudaGetSymbolAddress((void**)&pX1,  g_X1);
    cudaGetSymbolAddress((void**)&pX2,  g_X2);
    cudaGetSymbolAddress((void**)&pagg, g_agg);
    cudaGetSymbolAddress((void**)&pq,   g_q);
    cudaGetSymbolAddress((void**)&pk,   g_k);
    cudaGetSymbolAddress((void**)&pv,   g_v);
    cudaGetSymbolAddress((void**)&px,   g_x);
    cudaGetSymbolAddress((void**)&pt,   g_t);
    cudaGetSymbolAddress((void**)&pbsum, g_bsum);
    cudaGetSymbolAddress((void**)&prw,  g_rw);

    // graph preprocessing
    pack_deg_kernel<<<Nn * 128 / 256, 256>>>(h, ei);
    prefix_kernel<<<1, 1024>>>(b_src, b_tgt);
    fill_kernel<<<256, 256>>>(ei);
    aggsum_kernel<<<Nn / 2, 256>>>(h);   // 4 warps/node; partials X1,t,q,k

    dim3 gH(Hh / 64, Nn / 128);
    // agg = (X1a+X1b+X1c+X1d)@W_src + X2@W_tgt + rw*(b_src+b_tgt)
    mm_gemm<0><<<gH, 256>>>(pX1, pt, pq, pk, W_src, pX2, W_tgt, pbsum, prw,
                            pagg, Hh, Hh);

    // fused q/k/v projections -> bf16x2-packed (q pre-scaled)
    qkv_gemm<<<dim3(Hh / 64, Nn / 128, 3), 256>>>(
        h, pagg, Wq, Wk, Wv, bq, bk, bv,
        (uint32_t*)pq, (uint32_t*)pk, (uint32_t*)pv);

    // flash attention: split-K over 4 quarters (partials X1,X2,agg,t)
    cudaFuncSetAttribute(attn_kernel, cudaFuncAttributeMaxDynamicSharedMemorySize, ATT_SMEM);
    attn_kernel<<<dim3(Nn / 128, NHEADS, 4), 256, ATT_SMEM>>>(
        (const uint32_t*)pq, (const uint32_t*)pk, (const uint32_t*)pv,
        pX1, pX2, pagg, pt);

    // x = LN(h + ((O0+O1+O2+O3)*il)@Wo + bo)
    mm_gemm_ln<256, 1><<<Nn / 32, 256>>>(pX1, pX2, pagg, pt, Wo, bo, h, g1, be1, px);

    // FFN: t = gelu(x@W1 + b1) ; out = LN(x + t@W2 + b2)
    mm_gemm<1><<<dim3(2 * Hh / 64, Nn / 128), 256>>>(
        px, nullptr, nullptr, nullptr, W1, nullptr, nullptr, b1, nullptr, pt, Hh, 2 * Hh);
    mm_gemm_ln<512, 0><<<Nn / 32, 256>>>(pt, nullptr, nullptr, nullptr, W2, b2, px,
                                         g2, be2, out);

    (void)in_sizes; (void)n_in; (void)out_size;
}

// round 15
// speedup vs baseline: 1.0111x; 1.0111x over previous
#include <cuda_runtime.h>
#include <math.h>
#include <stdint.h>

// Problem constants: N=4096 nodes, H=256, HEADS=4, DH=64, E=262144, fp32.
#define Nn 4096
#define Hh 256
#define NHEADS 4
#define DHd 64
#define Ee 262144
#define QSC (0.125f * 1.4426950408889634f)
#define CSTRIDE 32

// ---------------- scratch (static device globals) ---------------------------
__device__ int      g_degs[Nn * CSTRIDE];
__device__ int      g_curs[Nn * CSTRIDE];
__device__ int      g_rowptr[Nn + 1];
__device__ int      g_col[Ee];
__device__ uint32_t g_hbf[Nn * 128];        // h packed bf16x2
__device__ float    g_rw[Nn];
__device__ float    g_bsum[Hh];
__device__ float    g_acc[2 * NHEADS * Nn]; // attention partial row-sums
__device__ float    g_X1[Nn * Hh];          // aggsum partial A / attn O-partial 0
__device__ float    g_X2[Nn * Hh];          // X2 / attn O-partial 1
__device__ float    g_agg[Nn * Hh];
__device__ float    g_q[Nn * Hh];    // u32 bf16x2-packed
__device__ float    g_k[Nn * Hh];    // "
__device__ float    g_v[Nn * Hh];    // "
__device__ float    g_x[Nn * Hh];
__device__ float    g_t[Nn * 2 * Hh]; // aggsum partial B during preproc; FFN mid

// ---------------- helpers -----------------------------------------------------
__device__ __forceinline__ uint32_t smem_u32(const void* p) {
    uint32_t a;
    asm("{ .reg .u64 t; cvta.to.shared.u64 t, %1; cvt.u32.u64 %0, t; }"
        : "=r"(a) : "l"(p));
    return a;
}
__device__ __forceinline__ uint32_t f2tf32(float x) {
    uint32_t r;
    asm("cvt.rna.tf32.f32 %0, %1;" : "=r"(r) : "f"(x));
    return r;
}
__device__ __forceinline__ float tf(float x) { return __uint_as_float(f2tf32(x)); }
__device__ __forceinline__ uint32_t bf2(float lo, float hi) {
    uint32_t r;
    asm("cvt.rn.bf16x2.f32 %0, %1, %2;" : "=r"(r) : "f"(hi), "f"(lo));
    return r;
}
__device__ __forceinline__ float ex2(float x) {
    float r;
    asm("ex2.approx.f32 %0, %1;" : "=f"(r) : "f"(x));
    return r;
}
__device__ __forceinline__ float blo(uint32_t u) { return __uint_as_float(u << 16); }
__device__ __forceinline__ float bhi(uint32_t u) { return __uint_as_float(u & 0xffff0000u); }

__device__ __forceinline__ void mma8(float* c, const uint32_t* a, uint32_t b0, uint32_t b1) {
    asm volatile(
        "mma.sync.aligned.m16n8k8.row.col.f32.tf32.tf32.f32 "
        "{%0,%1,%2,%3}, {%4,%5,%6,%7}, {%8,%9}, {%0,%1,%2,%3};"
        : "+f"(c[0]), "+f"(c[1]), "+f"(c[2]), "+f"(c[3])
        : "r"(a[0]), "r"(a[1]), "r"(a[2]), "r"(a[3]), "r"(b0), "r"(b1));
}
__device__ __forceinline__ void mmabf(float* c, const uint32_t* a, uint32_t b0, uint32_t b1) {
    asm volatile(
        "mma.sync.aligned.m16n8k16.row.col.f32.bf16.bf16.f32 "
        "{%0,%1,%2,%3}, {%4,%5,%6,%7}, {%8,%9}, {%0,%1,%2,%3};"
        : "+f"(c[0]), "+f"(c[1]), "+f"(c[2]), "+f"(c[3])
        : "r"(a[0]), "r"(a[1]), "r"(a[2]), "r"(a[3]), "r"(b0), "r"(b1));
}
__device__ __forceinline__ void ldsm4(uint32_t& r0, uint32_t& r1, uint32_t& r2,
                                      uint32_t& r3, uint32_t a) {
    asm volatile("ldmatrix.sync.aligned.m8n8.x4.shared.b16 {%0,%1,%2,%3}, [%4];"
                 : "=r"(r0), "=r"(r1), "=r"(r2), "=r"(r3) : "r"(a));
}
__device__ __forceinline__ void ldsm4t(uint32_t& r0, uint32_t& r1, uint32_t& r2,
                                       uint32_t& r3, uint32_t a) {
    asm volatile("ldmatrix.sync.aligned.m8n8.x4.trans.shared.b16 {%0,%1,%2,%3}, [%4];"
                 : "=r"(r0), "=r"(r1), "=r"(r2), "=r"(r3) : "r"(a));
}
__device__ __forceinline__ float gelu(float v) {
    return 0.5f * v * (1.0f + erff(v * 0.7071067811865476f));
}
#define CP_COMMIT() asm volatile("cp.async.commit_group;" ::: "memory")
#define CP_WAIT(n)  asm volatile("cp.async.wait_group %0;" :: "n"(n) : "memory")
#define CPA16(sm, g) \
    asm volatile("cp.async.cg.shared.global [%0], [%1], 16;" :: "r"(sm), "l"(g) : "memory")

// ---------------- graph preprocessing ---------------------------------------
__global__ void pack_deg_kernel(const float* __restrict__ h, const int* __restrict__ ei) {
    int i = blockIdx.x * blockDim.x + threadIdx.x;
    int row = i >> 7, col = i & 127;
    float2 hv = *(const float2*)(h + (size_t)row * Hh + col * 2);
    g_hbf[i] = bf2(hv.x, hv.y);
    if (i < 65536) {
        int idx[4];
#pragma unroll
        for (int j = 0; j < 4; j++) idx[j] = ei[Ee + i + j * 65536];
#pragma unroll
        for (int j = 0; j < 4; j++) atomicAdd(&g_degs[idx[j] * CSTRIDE], 1);
    }
}
__global__ void prefix_kernel(const float* __restrict__ bsrc, const float* __restrict__ btgt) {
    __shared__ int sm[1024];
    int t = threadIdx.x;
    if (t < Hh) g_bsum[t] = bsrc[t] + btgt[t];
    int b = t * 4;
    int d0 = g_degs[(b + 0) * CSTRIDE];
    int d1 = g_degs[(b + 1) * CSTRIDE];
    int d2 = g_degs[(b + 2) * CSTRIDE];
    int d3 = g_degs[(b + 3) * CSTRIDE];
    g_degs[(b + 0) * CSTRIDE] = 0;
    g_degs[(b + 1) * CSTRIDE] = 0;
    g_degs[(b + 2) * CSTRIDE] = 0;
    g_degs[(b + 3) * CSTRIDE] = 0;
    int tot = d0 + d1 + d2 + d3;
    sm[t] = tot;
    __syncthreads();
    for (int off = 1; off < 1024; off <<= 1) {
        int v = 0;
        if (t >= off) v = sm[t - off];
        __syncthreads();
        if (t >= off) sm[t] += v;
        __syncthreads();
    }
    int excl = sm[t] - tot;
    g_rowptr[b]     = excl; g_curs[(b + 0) * CSTRIDE] = excl; excl += d0;
    g_rowptr[b + 1] = excl; g_curs[(b + 1) * CSTRIDE] = excl; excl += d1;
    g_rowptr[b + 2] = excl; g_curs[(b + 2) * CSTRIDE] = excl; excl += d2;
    g_rowptr[b + 3] = excl; g_curs[(b + 3) * CSTRIDE] = excl; excl += d3;
    if (t == 1023) g_rowptr[Nn] = excl;
}
__global__ void fill_kernel(const int* __restrict__ ei) {
    int t = blockIdx.x * blockDim.x + threadIdx.x;
    int dst[4], src[4], pos[4];
#pragma unroll
    for (int i = 0; i < 4; i++) {
        dst[i] = ei[Ee + t + i * 65536];
        src[i] = ei[t + i * 65536];
    }
#pragma unroll
    for (int i = 0; i < 4; i++) pos[i] = atomicAdd(&g_curs[dst[i] * CSTRIDE], 1);
#pragma unroll
    for (int i = 0; i < 4; i++) g_col[pos[i]] = src[i];
}
// 2 warps per node (R12 config): warp `half` takes 8-edge chunks of parity
// `half`; warp 1 also handles the tail. Partials -> g_X1 / g_t.
__global__ void __launch_bounds__(256) aggsum_kernel(const float* __restrict__ h) {
    int wrp = threadIdx.x >> 5;
    int n = blockIdx.x * 4 + (wrp >> 1);
    int half = wrp & 1;
    int lane = threadIdx.x & 31;
    int s0 = g_rowptr[n], s1 = g_rowptr[n + 1];
    int d = s1 - s0;
    float inv = 1.0f / (float)max(d, 1);
    float rwv = d > 0 ? 1.0f : 0.0f;
    const uint4* hb = (const uint4*)g_hbf;

    float a[8] = {};
    for (int e = s0 + half * 8; e + 8 <= s1; e += 16) {
        int cc[8];
#pragma unroll
        for (int j = 0; j < 8; j++) cc[j] = g_col[e + j];
        uint4 u[8];
#pragma unroll
        for (int j = 0; j < 8; j++) u[j] = hb[(size_t)cc[j] * 32 + lane];
#pragma unroll
        for (int j = 0; j < 8; j++) {
            a[0] += blo(u[j].x); a[1] += bhi(u[j].x);
            a[2] += blo(u[j].y); a[3] += bhi(u[j].y);
            a[4] += blo(u[j].z); a[5] += bhi(u[j].z);
            a[6] += blo(u[j].w); a[7] += bhi(u[j].w);
        }
    }
    if (half == 1) {
        for (int e = s1 - (d & 7); e < s1; e++) {
            uint4 u0 = hb[(size_t)g_col[e] * 32 + lane];
            a[0] += blo(u0.x); a[1] += bhi(u0.x);
            a[2] += blo(u0.y); a[3] += bhi(u0.y);
            a[4] += blo(u0.z); a[5] += bhi(u0.z);
            a[6] += blo(u0.w); a[7] += bhi(u0.w);
        }
    }
    float* x1 = (half ? g_t : g_X1) + (size_t)n * Hh + lane * 8;
    *(float4*)x1       = make_float4(a[0] * inv, a[1] * inv, a[2] * inv, a[3] * inv);
    *(float4*)(x1 + 4) = make_float4(a[4] * inv, a[5] * inv, a[6] * inv, a[7] * inv);
    if (half == 0) {
        const float* hr = h + (size_t)n * Hh + lane * 8;
        float4 h0 = *(const float4*)hr;
        float4 h1 = *(const float4*)(hr + 4);
        float* x2 = g_X2 + (size_t)n * Hh + lane * 8;
        *(float4*)x2       = make_float4(h0.x * rwv, h0.y * rwv, h0.z * rwv, h0.w * rwv);
        *(float4*)(x2 + 4) = make_float4(h1.x * rwv, h1.y * rwv, h1.z * rwv, h1.w * rwv);
        if (lane == 0) g_rw[n] = rwv;
    }
}

// ---------------- tf32 mma.sync GEMM (fp32 out) --------------------------------
// C = (A [+Acb elementwise]) @ B (+ A2@B2) (+ bias[n]*rowScale[m]) ; ACT=1: gelu
template <int ACT>
__global__ void __launch_bounds__(256) mm_gemm(
    const float* __restrict__ A, const float* __restrict__ Acb,
    const float* __restrict__ B,
    const float* __restrict__ A2, const float* __restrict__ B2,
    const float* __restrict__ bias, const float* __restrict__ rowScale,
    float* __restrict__ C, int K, int Nc)
{
    __shared__ __align__(16) float As[128 * 36];
    __shared__ __align__(16) float Bs[32 * 72];
    int tid = threadIdx.x, wid = tid >> 5, lane = tid & 31;
    int gid = lane >> 2, tg = lane & 3;
    int moff = (wid & 3) * 32, noff = (wid >> 2) * 32;
    int m0 = blockIdx.y * 128, n0 = blockIdx.x * 64;

    float c[2][4][4] = {};
    int steps1 = K / 32;
    int steps = A2 ? 2 * steps1 : steps1;

    float4 ra[4], rcb[4], rb[2];
    {
#pragma unroll
        for (int i = 0; i < 4; i++) {
            int f = tid + i * 256, m = f >> 3, qq = f & 7;
            ra[i] = *(const float4*)(A + (size_t)(m0 + m) * K + qq * 4);
            if (Acb) rcb[i] = *(const float4*)(Acb + (size_t)(m0 + m) * K + qq * 4);
        }
#pragma unroll
        for (int i = 0; i < 2; i++) {
            int f = tid + i * 256, kk = f >> 4, qq = f & 15;
            rb[i] = *(const float4*)(B + (size_t)kk * Nc + n0 + qq * 4);
        }
    }

    for (int s = 0; s < steps; s++) {
        bool cmb = Acb && (s < steps1);
        __syncthreads();
#pragma unroll
        for (int i = 0; i < 4; i++) {
            int f = tid + i * 256, m = f >> 3, qq = f & 7;
            float4 v = ra[i];
            if (cmb) {
                v.x += rcb[i].x; v.y += rcb[i].y;
                v.z += rcb[i].z; v.w += rcb[i].w;
            }
            *(float4*)&As[m * 36 + qq * 4] =
                make_float4(tf(v.x), tf(v.y), tf(v.z), tf(v.w));
        }
#pragma unroll
        for (int i = 0; i < 2; i++) {
            int f = tid + i * 256, kk = f >> 4, qq = f & 15;
            *(float4*)&Bs[kk * 72 + qq * 4] =
                make_float4(tf(rb[i].x), tf(rb[i].y), tf(rb[i].z), tf(rb[i].w));
        }
        __syncthreads();
        if (s + 1 < steps) {
            int s2 = s + 1;
            const float* Ag = (s2 < steps1) ? A : A2;
            const float* Bg = (s2 < steps1) ? B : B2;
            int k0 = ((s2 < steps1) ? s2 : (s2 - steps1)) * 32;
#pragma unroll
            for (int i = 0; i < 4; i++) {
                int f = tid + i * 256, m = f >> 3, qq = f & 7;
                ra[i] = *(const float4*)(Ag + (size_t)(m0 + m) * K + k0 + qq * 4);
                if (Acb && s2 < steps1)
                    rcb[i] = *(const float4*)(Acb + (size_t)(m0 + m) * K + k0 + qq * 4);
            }
#pragma unroll
            for (int i = 0; i < 2; i++) {
                int f = tid + i * 256, kk = f >> 4, qq = f & 15;
                rb[i] = *(const float4*)(Bg + (size_t)(k0 + kk) * Nc + n0 + qq * 4);
            }
        }
#pragma unroll
        for (int ks = 0; ks < 4; ks++) {
            int ck = ks * 8 + tg;
            uint32_t a0[4], a1[4];
            a0[0] = __float_as_uint(As[(moff + gid) * 36 + ck]);
            a0[1] = __float_as_uint(As[(moff + gid + 8) * 36 + ck]);
            a0[2] = __float_as_uint(As[(moff + gid) * 36 + ck + 4]);
            a0[3] = __float_as_uint(As[(moff + gid + 8) * 36 + ck + 4]);
            a1[0] = __float_as_uint(As[(moff + 16 + gid) * 36 + ck]);
            a1[1] = __float_as_uint(As[(moff + 24 + gid) * 36 + ck]);
            a1[2] = __float_as_uint(As[(moff + 16 + gid) * 36 + ck + 4]);
            a1[3] = __float_as_uint(As[(moff + 24 + gid) * 36 + ck + 4]);
#pragma unroll
            for (int jn = 0; jn < 4; jn++) {
                uint32_t b0 = __float_as_uint(Bs[ck * 72 + noff + jn * 8 + gid]);
                uint32_t b1 = __float_as_uint(Bs[(ck + 4) * 72 + noff + jn * 8 + gid]);
                mma8(c[0][jn], a0, b0, b1);
                mma8(c[1][jn], a1, b0, b1);
            }
        }
    }

#pragma unroll
    for (int im = 0; im < 2; im++) {
        int r1 = m0 + moff + im * 16 + gid, r2 = r1 + 8;
        float rs1 = rowScale ? rowScale[r1] : 1.0f;
        float rs2 = rowScale ? rowScale[r2] : 1.0f;
#pragma unroll
        for (int jn = 0; jn < 4; jn++) {
            int col = n0 + noff + jn * 8 + 2 * tg;
            float v00 = c[im][jn][0], v01 = c[im][jn][1];
            float v10 = c[im][jn][2], v11 = c[im][jn][3];
            if (bias) {
                float bb0 = bias[col], bb1 = bias[col + 1];
                v00 += bb0 * rs1; v01 += bb1 * rs1;
                v10 += bb0 * rs2; v11 += bb1 * rs2;
            }
            if (ACT == 1) {
                v00 = gelu(v00); v01 = gelu(v01);
                v10 = gelu(v10); v11 = gelu(v11);
            }
            *(float2*)(C + (size_t)r1 * Nc + col) = make_float2(v00, v01);
            *(float2*)(C + (size_t)r2 * Nc + col) = make_float2(v10, v11);
        }
    }
}

// ---------------- tf32 GEMM with fused residual + layernorm --------------------
// 16-row CTA tile (grid = Nn/16 = 256, full wave). All 8 warps share one m16
// block; warp w covers cols [w*32, w*32+32). C = LN(res + Acomb@B + bias),
// Acomb = COMBINE ? (A+A2)*il : A.
template <int KK, int COMBINE>
__global__ void __launch_bounds__(256) mm_gemm_ln(
    const float* __restrict__ A, const float* __restrict__ A2,
    const float* __restrict__ B,
    const float* __restrict__ bias, const float* __restrict__ res,
    const float* __restrict__ g, const float* __restrict__ be,
    float* __restrict__ C)
{
    __shared__ __align__(16) float As[16 * 36];
    __shared__ __align__(16) float Bs[32 * 264];
    __shared__ float redS[16 * 8], redQ[16 * 8];
    int tid = threadIdx.x, wid = tid >> 5, lane = tid & 31;
    int gid = lane >> 2, tg = lane & 3;
    int noff = wid * 32;
    int m0 = blockIdx.x * 16;
    const int steps = KK / 32;
    int am = tid >> 3, aq = tid & 7;   // A-stage (threads 0..127)
    bool ast = tid < 128;

    float il[4];
    if (COMBINE && ast) {
        int r = m0 + am;
#pragma unroll
        for (int hd = 0; hd < 4; hd++)
            il[hd] = 1.0f / (g_acc[hd * Nn + r] + g_acc[(NHEADS + hd) * Nn + r]);
    }

    float c[4][4] = {};
    float4 ra, ra2, rb[8];
    {
        if (ast) {
            size_t off = (size_t)(m0 + am) * KK + aq * 4;
            ra = *(const float4*)(A + off);
            if (COMBINE) ra2 = *(const float4*)(A2 + off);
        }
#pragma unroll
        for (int i = 0; i < 8; i++) {
            int f = tid + i * 256, kk = f >> 6, q2 = f & 63;
            rb[i] = *(const float4*)(B + (size_t)kk * Hh + q2 * 4);
        }
    }
    for (int s = 0; s < steps; s++) {
        __syncthreads();
        if (ast) {
            float4 v = ra;
            if (COMBINE) {
                float sc = il[s >> 1];
                v = make_float4((ra.x + ra2.x) * sc, (ra.y + ra2.y) * sc,
                                (ra.z + ra2.z) * sc, (ra.w + ra2.w) * sc);
            }
            *(float4*)&As[am * 36 + aq * 4] =
                make_float4(tf(v.x), tf(v.y), tf(v.z), tf(v.w));
        }
#pragma unroll
        for (int i = 0; i < 8; i++) {
            int f = tid + i * 256, kk = f >> 6, q2 = f & 63;
            *(float4*)&Bs[kk * 264 + q2 * 4] =
                make_float4(tf(rb[i].x), tf(rb[i].y), tf(rb[i].z), tf(rb[i].w));
        }
        __syncthreads();
        if (s + 1 < steps) {
            int k0 = (s + 1) * 32;
            if (ast) {
                size_t off = (size_t)(m0 + am) * KK + k0 + aq * 4;
                ra = *(const float4*)(A + off);
                if (COMBINE) ra2 = *(const float4*)(A2 + off);
            }
#pragma unroll
            for (int i = 0; i < 8; i++) {
                int f = tid + i * 256, kk = f >> 6, q2 = f & 63;
                rb[i] = *(const float4*)(B + (size_t)(k0 + kk) * Hh + q2 * 4);
            }
        }
#pragma unroll
        for (int ks = 0; ks < 4; ks++) {
            int ck = ks * 8 + tg;
            uint32_t a0[4];
            a0[0] = __float_as_uint(As[gid * 36 + ck]);
            a0[1] = __float_as_uint(As[(gid + 8) * 36 + ck]);
            a0[2] = __float_as_uint(As[gid * 36 + ck + 4]);
            a0[3] = __float_as_uint(As[(gid + 8) * 36 + ck + 4]);
#pragma unroll
            for (int jn = 0; jn < 4; jn++) {
                uint32_t b0 = __float_as_uint(Bs[ck * 264 + noff + jn * 8 + gid]);
                uint32_t b1 = __float_as_uint(Bs[(ck + 4) * 264 + noff + jn * 8 + gid]);
                mma8(c[jn], a0, b0, b1);
            }
        }
    }

    // epilogue: add bias + residual, LN across 256 cols (8 warps x 32 cols)
    int r1 = m0 + gid, r2 = r1 + 8;
    float s1 = 0, q1 = 0, s2 = 0, q2 = 0;
#pragma unroll
    for (int jn = 0; jn < 4; jn++) {
        int col = noff + jn * 8 + 2 * tg;
        float2 rr1 = *(const float2*)(res + (size_t)r1 * Hh + col);
        float2 rr2 = *(const float2*)(res + (size_t)r2 * Hh + col);
        float bb0 = bias[col], bb1 = bias[col + 1];
        c[jn][0] += bb0 + rr1.x; c[jn][1] += bb1 + rr1.y;
        c[jn][2] += bb0 + rr2.x; c[jn][3] += bb1 + rr2.y;
        s1 += c[jn][0] + c[jn][1];
        q1 += c[jn][0] * c[jn][0] + c[jn][1] * c[jn][1];
        s2 += c[jn][2] + c[jn][3];
        q2 += c[jn][2] * c[jn][2] + c[jn][3] * c[jn][3];
    }
    s1 += __shfl_xor_sync(0xffffffffu, s1, 1); s1 += __shfl_xor_sync(0xffffffffu, s1, 2);
    q1 += __shfl_xor_sync(0xffffffffu, q1, 1); q1 += __shfl_xor_sync(0xffffffffu, q1, 2);
    s2 += __shfl_xor_sync(0xffffffffu, s2, 1); s2 += __shfl_xor_sync(0xffffffffu, s2, 2);
    q2 += __shfl_xor_sync(0xffffffffu, q2, 1); q2 += __shfl_xor_sync(0xffffffffu, q2, 2);
    if (tg == 0) {
        redS[gid * 8 + wid] = s1;
        redQ[gid * 8 + wid] = q1;
        redS[(gid + 8) * 8 + wid] = s2;
        redQ[(gid + 8) * 8 + wid] = q2;
    }
    __syncthreads();
    float su1 = 0, qu1 = 0, su2 = 0, qu2 = 0;
#pragma unroll
    for (int i = 0; i < 8; i++) {
        su1 += redS[gid * 8 + i];
        qu1 += redQ[gid * 8 + i];
        su2 += redS[(gid + 8) * 8 + i];
        qu2 += redQ[(gid + 8) * 8 + i];
    }
    float mu1 = su1 * (1.0f / Hh), mu2 = su2 * (1.0f / Hh);
    float rstd1 = rsqrtf(qu1 * (1.0f / Hh) - mu1 * mu1 + 1e-5f);
    float rstd2 = rsqrtf(qu2 * (1.0f / Hh) - mu2 * mu2 + 1e-5f);
#pragma unroll
    for (int jn = 0; jn < 4; jn++) {
        int col = noff + jn * 8 + 2 * tg;
        float g0 = g[col], g1v = g[col + 1];
        float e0 = be[col], e1 = be[col + 1];
        *(float2*)(C + (size_t)r1 * Hh + col) = make_float2(
            (c[jn][0] - mu1) * rstd1 * g0 + e0, (c[jn][1] - mu1) * rstd1 * g1v + e1);
        *(float2*)(C + (size_t)r2 * Hh + col) = make_float2(
            (c[jn][2] - mu2) * rstd2 * g0 + e0, (c[jn][3] - mu2) * rstd2 * g1v + e1);
    }
}

// ---------------- fused QKV projection (tf32 mma, bf16x2-packed out) -----------
__global__ void __launch_bounds__(256) qkv_gemm(
    const float* __restrict__ h, const float* __restrict__ agg,
    const float* __restrict__ Wq, const float* __restrict__ Wk,
    const float* __restrict__ Wv,
    const float* __restrict__ bq, const float* __restrict__ bk,
    const float* __restrict__ bv,
    uint32_t* __restrict__ qo, uint32_t* __restrict__ ko, uint32_t* __restrict__ vo)
{
    __shared__ __align__(16) float As[128 * 36];
    __shared__ __align__(16) float Bs[32 * 72];
    int z = blockIdx.z;
    const float* A    = (z == 0) ? h  : agg;
    const float* B    = (z == 0) ? Wq : (z == 1 ? Wk : Wv);
    const float* bias = (z == 0) ? bq : (z == 1 ? bk : bv);
    uint32_t*    C    = (z == 0) ? qo : (z == 1 ? ko : vo);
    float osc = (z == 0) ? QSC : 1.0f;

    int tid = threadIdx.x, wid = tid >> 5, lane = tid & 31;
    int gid = lane >> 2, tg = lane & 3;
    int moff = (wid & 3) * 32, noff = (wid >> 2) * 32;
    int m0 = blockIdx.y * 128, n0 = blockIdx.x * 64;

    float c[2][4][4] = {};
    float4 ra[4], rb[2];
#pragma unroll
    for (int i = 0; i < 4; i++) {
        int f = tid + i * 256, m = f >> 3, qq = f & 7;
        ra[i] = *(const float4*)(A + (size_t)(m0 + m) * Hh + qq * 4);
    }
#pragma unroll
    for (int i = 0; i < 2; i++) {
        int f = tid + i * 256, kk = f >> 4, qq = f & 15;
        rb[i] = *(const float4*)(B + (size_t)kk * Hh + n0 + qq * 4);
    }

#pragma unroll
    for (int s = 0; s < 8; s++) {
        __syncthreads();
#pragma unroll
        for (int i = 0; i < 4; i++) {
            int f = tid + i * 256, m = f >> 3, qq = f & 7;
            *(float4*)&As[m * 36 + qq * 4] =
                make_float4(tf(ra[i].x), tf(ra[i].y), tf(ra[i].z), tf(ra[i].w));
        }
#pragma unroll
        for (int i = 0; i < 2; i++) {
            int f = tid + i * 256, kk = f >> 4, qq = f & 15;
            *(float4*)&Bs[kk * 72 + qq * 4] =
                make_float4(tf(rb[i].x), tf(rb[i].y), tf(rb[i].z), tf(rb[i].w));
        }
        __syncthreads();
        if (s + 1 < 8) {
            int k0 = (s + 1) * 32;
#pragma unroll
            for (int i = 0; i < 4; i++) {
                int f = tid + i * 256, m = f >> 3, qq = f & 7;
                ra[i] = *(const float4*)(A + (size_t)(m0 + m) * Hh + k0 + qq * 4);
            }
#pragma unroll
            for (int i = 0; i < 2; i++) {
                int f = tid + i * 256, kk = f >> 4, qq = f & 15;
                rb[i] = *(const float4*)(B + (size_t)(k0 + kk) * Hh + n0 + qq * 4);
            }
        }
#pragma unroll
        for (int ks = 0; ks < 4; ks++) {
            int ck = ks * 8 + tg;
            uint32_t a0[4], a1[4];
            a0[0] = __float_as_uint(As[(moff + gid) * 36 + ck]);
            a0[1] = __float_as_uint(As[(moff + gid + 8) * 36 + ck]);
            a0[2] = __float_as_uint(As[(moff + gid) * 36 + ck + 4]);
            a0[3] = __float_as_uint(As[(moff + gid + 8) * 36 + ck + 4]);
            a1[0] = __float_as_uint(As[(moff + 16 + gid) * 36 + ck]);
            a1[1] = __float_as_uint(As[(moff + 24 + gid) * 36 + ck]);
            a1[2] = __float_as_uint(As[(moff + 16 + gid) * 36 + ck + 4]);
            a1[3] = __float_as_uint(As[(moff + 24 + gid) * 36 + ck + 4]);
#pragma unroll
            for (int jn = 0; jn < 4; jn++) {
                uint32_t b0 = __float_as_uint(Bs[ck * 72 + noff + jn * 8 + gid]);
                uint32_t b1 = __float_as_uint(Bs[(ck + 4) * 72 + noff + jn * 8 + gid]);
                mma8(c[0][jn], a0, b0, b1);
                mma8(c[1][jn], a1, b0, b1);
            }
        }
    }

#pragma unroll
    for (int im = 0; im < 2; im++) {
        int r1 = m0 + moff + im * 16 + gid, r2 = r1 + 8;
#pragma unroll
        for (int jn = 0; jn < 4; jn++) {
            int col = n0 + noff + jn * 8 + 2 * tg;
            float bb0 = bias[col], bb1 = bias[col + 1];
            C[(size_t)r1 * (Hh / 2) + (col >> 1)] =
                bf2((c[im][jn][0] + bb0) * osc, (c[im][jn][1] + bb1) * osc);
            C[(size_t)r2 * (Hh / 2) + (col >> 1)] =
                bf2((c[im][jn][2] + bb0) * osc, (c[im][jn][3] + bb1) * osc);
        }
    }
}

// ---------------- flash attention (bf16 mma, split-K over 2 halves) ------------
#define AP 36
#define ATILE (64 * AP)
#define NBUF 4
#define ATT_SMEM (NBUF * 2 * ATILE * 4)
#define NT_HALF (Nn / 128)  // 32 tiles per half
__device__ __forceinline__ void attn_issue(uint32_t sbase, int buf,
                                           const uint32_t* kbf, const uint32_t* vbf,
                                           int t, int hd, int tid) {
    uint32_t Kb = sbase + (uint32_t)buf * (2 * ATILE * 4);
    uint32_t Vb = Kb + ATILE * 4;
#pragma unroll
    for (int i = 0; i < 2; i++) {
        int f = tid + i * 256, r = f >> 3, ch = f & 7;
        const uint32_t* kg = kbf + (size_t)(t * 64 + r) * 128 + hd * 32 + ch * 4;
        const uint32_t* vg = vbf + (size_t)(t * 64 + r) * 128 + hd * 32 + ch * 4;
        uint32_t so = (uint32_t)(r * AP + ch * 4) * 4u;
        CPA16(Kb + so, kg);
        CPA16(Vb + so, vg);
    }
}

__global__ void __launch_bounds__(256) attn_kernel(
    const uint32_t* __restrict__ qbf, const uint32_t* __restrict__ kbf,
    const uint32_t* __restrict__ vbf,
    float* __restrict__ o0, float* __restrict__ o1)
{
    extern __shared__ __align__(16) uint32_t smt[];
    uint32_t sbase = smem_u32(smt);
    int tid = threadIdx.x, wid = tid >> 5, lane = tid & 31;
    int gid = lane >> 2, tg = lane & 3;
    int l8 = lane >> 3, lr = lane & 7;
    int hd = blockIdx.y;
    int z = blockIdx.z;
    int q0 = blockIdx.x * 128;
    int wrow = wid * 16;
    int t0 = z * NT_HALF;

    uint32_t koff = (uint32_t)(((l8 >> 1) * 8 + lr) * AP + (l8 & 1) * 4) * 4u;
    uint32_t voff = (uint32_t)((l8 * 8 + lr) * AP) * 4u;

    uint32_t qa[4][4];
    {
        const uint32_t* q1 = qbf + (size_t)(q0 + wrow + gid) * 128 + hd * 32;
        const uint32_t* q2 = q1 + 8 * 128;
#pragma unroll
        for (int ks = 0; ks < 4; ks++) {
            qa[ks][0] = q1[ks * 8 + tg];
            qa[ks][1] = q2[ks * 8 + tg];
            qa[ks][2] = q1[ks * 8 + tg + 4];
            qa[ks][3] = q2[ks * 8 + tg + 4];
        }
    }

    attn_issue(sbase, 0, kbf, vbf, t0, hd, tid); CP_COMMIT();
    attn_issue(sbase, 1, kbf, vbf, t0 + 1, hd, tid); CP_COMMIT();

    float o[8][4] = {};
    float acc0 = 0.0f, acc1 = 0.0f;

    for (int ti = 0; ti < NT_HALF; ti++) {
        if (ti + 2 < NT_HALF) {
            attn_issue(sbase, (ti + 2) & (NBUF - 1), kbf, vbf, t0 + ti + 2, hd, tid);
            CP_COMMIT();
            CP_WAIT(2);
        } else if (ti + 1 < NT_HALF) {
            CP_WAIT(1);
        } else {
            CP_WAIT(0);
        }
        __syncthreads();
        uint32_t Kb = sbase + (uint32_t)(ti & (NBUF - 1)) * (2 * ATILE * 4);
        uint32_t Vb = Kb + ATILE * 4;

        // S = Q @ K^T
        float s[8][4] = {};
#pragma unroll
        for (int kb = 0; kb < 4; kb++) {
#pragma unroll
            for (int jnp = 0; jnp < 4; jnp++) {
                uint32_t b0, b1, b2, b3;
                uint32_t addr = Kb + koff + (uint32_t)(jnp * 16 * AP + kb * 8) * 4u;
                ldsm4(b0, b1, b2, b3, addr);
                mmabf(s[2 * jnp],     qa[kb], b0, b1);
                mmabf(s[2 * jnp + 1], qa[kb], b2, b3);
            }
        }

        // no-max softmax
        uint32_t pa[4][4];
#pragma unroll
        for (int jn = 0; jn < 8; jn++) {
            s[jn][0] = ex2(s[jn][0]);
            s[jn][1] = ex2(s[jn][1]);
            s[jn][2] = ex2(s[jn][2]);
            s[jn][3] = ex2(s[jn][3]);
            acc0 += s[jn][0] + s[jn][1];
            acc1 += s[jn][2] + s[jn][3];
        }
#pragma unroll
        for (int ks = 0; ks < 4; ks++) {
            pa[ks][0] = bf2(s[2 * ks][0], s[2 * ks][1]);
            pa[ks][1] = bf2(s[2 * ks][2], s[2 * ks][3]);
            pa[ks][2] = bf2(s[2 * ks + 1][0], s[2 * ks + 1][1]);
            pa[ks][3] = bf2(s[2 * ks + 1][2], s[2 * ks + 1][3]);
        }

        // O += P @ V
#pragma unroll
        for (int jn = 0; jn < 8; jn++) {
#pragma unroll
            for (int ksp = 0; ksp < 2; ksp++) {
                uint32_t b0, b1, b2, b3;
                uint32_t addr = Vb + voff + (uint32_t)(ksp * 32 * AP + jn * 4) * 4u;
                ldsm4t(b0, b1, b2, b3, addr);
                mmabf(o[jn], pa[2 * ksp],     b0, b1);
                mmabf(o[jn], pa[2 * ksp + 1], b2, b3);
            }
        }
    }

    // partial epilogue: row sums + unnormalized O
    acc0 += __shfl_xor_sync(0xffffffffu, acc0, 1);
    acc0 += __shfl_xor_sync(0xffffffffu, acc0, 2);
    acc1 += __shfl_xor_sync(0xffffffffu, acc1, 1);
    acc1 += __shfl_xor_sync(0xffffffffu, acc1, 2);
    float* od = z ? o1 : o0;
    int r1 = q0 + wrow + gid, r2 = r1 + 8;
    if (tg == 0) {
        g_acc[(z * NHEADS + hd) * Nn + r1] = acc0;
        g_acc[(z * NHEADS + hd) * Nn + r2] = acc1;
    }
#pragma unroll
    for (int jn = 0; jn < 8; jn++) {
        int col = hd * DHd + jn * 8 + 2 * tg;
        *(float2*)(od + (size_t)r1 * Hh + col) = make_float2(o[jn][0], o[jn][1]);
        *(float2*)(od + (size_t)r2 * Hh + col) = make_float2(o[jn][2], o[jn][3]);
    }
}

// ---------------- launch ------------------------------------------------------
extern "C" void kernel_launch(void* const* d_in, const int* in_sizes, int n_in,
                              void* d_out, int out_size)
{
    const float* h     = (const float*)d_in[0];
    const int*   ei    = (const int*)d_in[1];
    const float* W_src = (const float*)d_in[2];
    const float* b_src = (const float*)d_in[3];
    const float* W_tgt = (const float*)d_in[4];
    const float* b_tgt = (const float*)d_in[5];
    const float* Wq = (const float*)d_in[6];  const float* bq = (const float*)d_in[7];
    const float* Wk = (const float*)d_in[8];  const float* bk = (const float*)d_in[9];
    const float* Wv = (const float*)d_in[10]; const float* bv = (const float*)d_in[11];
    const float* Wo = (const float*)d_in[12]; const float* bo = (const float*)d_in[13];
    const float* W1 = (const float*)d_in[14]; const float* b1 = (const float*)d_in[15];
    const float* W2 = (const float*)d_in[16]; const float* b2 = (const float*)d_in[17];
    const float* g1 = (const float*)d_in[18]; const float* be1 = (const float*)d_in[19];
    const float* g2 = (const float*)d_in[20]; const float* be2 = (const float*)d_in[21];
    float* out = (float*)d_out;

    float *pX1, *pX2, *pagg, *pq, *pk, *pv, *px, *pt, *pbsum, *prw;
    cudaGetSymbolAddress((void**)&pX1,  g_X1);
    cudaGetSymbolAddress((void**)&pX2,  g_X2);
    cudaGetSymbolAddress((void**)&pagg, g_agg);
    cudaGetSymbolAddress((void**)&pq,   g_q);
    cudaGetSymbolAddress((void**)&pk,   g_k);
    cudaGetSymbolAddress((void**)&pv,   g_v);
    cudaGetSymbolAddress((void**)&px,   g_x);
    cudaGetSymbolAddress((void**)&pt,   g_t);
    cudaGetSymbolAddress((void**)&pbsum, g_bsum);
    cudaGetSymbolAddress((void**)&prw,  g_rw);

    // graph preprocessing (R12 config)
    pack_deg_kernel<<<Nn * 128 / 256, 256>>>(h, ei);
    prefix_kernel<<<1, 1024>>>(b_src, b_tgt);
    fill_kernel<<<256, 256>>>(ei);
    aggsum_kernel<<<Nn / 4, 256>>>(h);   // 2 warps/node; partials in X1 + t

    dim3 gH(Hh / 64, Nn / 128);
    // agg = (X1a + X1b)@W_src + X2@W_tgt + rw*(b_src+b_tgt)
    mm_gemm<0><<<gH, 256>>>(pX1, pt, W_src, pX2, W_tgt, pbsum, prw, pagg, Hh, Hh);

    // fused q/k/v projections -> bf16x2-packed (q pre-scaled)
    qkv_gemm<<<dim3(Hh / 64, Nn / 128, 3), 256>>>(
        h, pagg, Wq, Wk, Wv, bq, bk, bv,
        (uint32_t*)pq, (uint32_t*)pk, (uint32_t*)pv);

    // flash attention: split-K over 2 halves (X1/X2 reused as O partials)
    cudaFuncSetAttribute(attn_kernel, cudaFuncAttributeMaxDynamicSharedMemorySize, ATT_SMEM);
    attn_kernel<<<dim3(Nn / 128, NHEADS, 2), 256, ATT_SMEM>>>(
        (const uint32_t*)pq, (const uint32_t*)pk, (const uint32_t*)pv, pX1, pX2);

    // x = LN(h + ((O0+O1)*il)@Wo + bo)  -- combine fused, 16-row tiles
    mm_gemm_ln<256, 1><<<Nn / 16, 256>>>(pX1, pX2, Wo, bo, h, g1, be1, px);

    // FFN: t = gelu(x@W1 + b1) ; out = LN(x + t@W2 + b2)  -- 16-row LN tiles
    mm_gemm<1><<<dim3(2 * Hh / 64, Nn / 128), 256>>>(
        px, nullptr, W1, nullptr, nullptr, b1, nullptr, pt, Hh, 2 * Hh);
    mm_gemm_ln<512, 0><<<Nn / 16, 256>>>(pt, nullptr, W2, b2, px, g2, be2, out);

    (void)in_sizes; (void)n_in; (void)out_size;
}

// round 16
// speedup vs baseline: 1.0336x; 1.0223x over previous
#include <cuda_runtime.h>
#include <math.h>
#include <stdint.h>

// Problem constants: N=4096 nodes, H=256, HEADS=4, DH=64, E=262144, fp32.
#define Nn 4096
#define Hh 256
#define NHEADS 4
#define DHd 64
#define Ee 262144
#define QSC (0.125f * 1.4426950408889634f)
#define CSTRIDE 32

// ---------------- scratch (static device globals) ---------------------------
__device__ int      g_degs[Nn * CSTRIDE];
__device__ int      g_curs[Nn * CSTRIDE];
__device__ int      g_rowptr[Nn + 1];
__device__ int      g_col[Ee];
__device__ uint32_t g_hbf[Nn * 128];        // h packed bf16x2
__device__ float    g_rw[Nn];
__device__ float    g_bsum[Hh];
__device__ float    g_acc[2 * NHEADS * Nn]; // attention partial row-sums
__device__ float    g_X1[Nn * Hh];          // aggsum partial A / attn O-partial 0
__device__ float    g_X2[Nn * Hh];          // attn O-partial 1
__device__ float    g_agg[Nn * Hh];
__device__ float    g_q[Nn * Hh];    // u32 bf16x2-packed
__device__ float    g_k[Nn * Hh];    // "
__device__ float    g_v[Nn * Hh];    // "
__device__ float    g_x[Nn * Hh];
__device__ float    g_t[Nn * 2 * Hh]; // aggsum partial B during preproc; FFN mid

// ---------------- helpers -----------------------------------------------------
__device__ __forceinline__ uint32_t smem_u32(const void* p) {
    uint32_t a;
    asm("{ .reg .u64 t; cvta.to.shared.u64 t, %1; cvt.u32.u64 %0, t; }"
        : "=r"(a) : "l"(p));
    return a;
}
__device__ __forceinline__ uint32_t f2tf32(float x) {
    uint32_t r;
    asm("cvt.rna.tf32.f32 %0, %1;" : "=r"(r) : "f"(x));
    return r;
}
__device__ __forceinline__ float tf(float x) { return __uint_as_float(f2tf32(x)); }
__device__ __forceinline__ uint32_t bf2(float lo, float hi) {
    uint32_t r;
    asm("cvt.rn.bf16x2.f32 %0, %1, %2;" : "=r"(r) : "f"(hi), "f"(lo));
    return r;
}
__device__ __forceinline__ float ex2(float x) {
    float r;
    asm("ex2.approx.f32 %0, %1;" : "=f"(r) : "f"(x));
    return r;
}
__device__ __forceinline__ float blo(uint32_t u) { return __uint_as_float(u << 16); }
__device__ __forceinline__ float bhi(uint32_t u) { return __uint_as_float(u & 0xffff0000u); }

__device__ __forceinline__ void mma8(float* c, const uint32_t* a, uint32_t b0, uint32_t b1) {
    asm volatile(
        "mma.sync.aligned.m16n8k8.row.col.f32.tf32.tf32.f32 "
        "{%0,%1,%2,%3}, {%4,%5,%6,%7}, {%8,%9}, {%0,%1,%2,%3};"
        : "+f"(c[0]), "+f"(c[1]), "+f"(c[2]), "+f"(c[3])
        : "r"(a[0]), "r"(a[1]), "r"(a[2]), "r"(a[3]), "r"(b0), "r"(b1));
}
__device__ __forceinline__ void mmabf(float* c, const uint32_t* a, uint32_t b0, uint32_t b1) {
    asm volatile(
        "mma.sync.aligned.m16n8k16.row.col.f32.bf16.bf16.f32 "
        "{%0,%1,%2,%3}, {%4,%5,%6,%7}, {%8,%9}, {%0,%1,%2,%3};"
        : "+f"(c[0]), "+f"(c[1]), "+f"(c[2]), "+f"(c[3])
        : "r"(a[0]), "r"(a[1]), "r"(a[2]), "r"(a[3]), "r"(b0), "r"(b1));
}
__device__ __forceinline__ void ldsm4(uint32_t& r0, uint32_t& r1, uint32_t& r2,
                                      uint32_t& r3, uint32_t a) {
    asm volatile("ldmatrix.sync.aligned.m8n8.x4.shared.b16 {%0,%1,%2,%3}, [%4];"
                 : "=r"(r0), "=r"(r1), "=r"(r2), "=r"(r3) : "r"(a));
}
__device__ __forceinline__ void ldsm4t(uint32_t& r0, uint32_t& r1, uint32_t& r2,
                                       uint32_t& r3, uint32_t a) {
    asm volatile("ldmatrix.sync.aligned.m8n8.x4.trans.shared.b16 {%0,%1,%2,%3}, [%4];"
                 : "=r"(r0), "=r"(r1), "=r"(r2), "=r"(r3) : "r"(a));
}
__device__ __forceinline__ float gelu(float v) {
    return 0.5f * v * (1.0f + erff(v * 0.7071067811865476f));
}
#define CP_COMMIT() asm volatile("cp.async.commit_group;" ::: "memory")
#define CP_WAIT(n)  asm volatile("cp.async.wait_group %0;" :: "n"(n) : "memory")
#define CPA16(sm, g) \
    asm volatile("cp.async.cg.shared.global [%0], [%1], 16;" :: "r"(sm), "l"(g) : "memory")

// ---------------- graph preprocessing ---------------------------------------
__global__ void pack_deg_kernel(const float* __restrict__ h, const int* __restrict__ ei) {
    int i = blockIdx.x * blockDim.x + threadIdx.x;
    int row = i >> 7, col = i & 127;
    float2 hv = *(const float2*)(h + (size_t)row * Hh + col * 2);
    g_hbf[i] = bf2(hv.x, hv.y);
    if (i < 65536) {
        int idx[4];
#pragma unroll
        for (int j = 0; j < 4; j++) idx[j] = ei[Ee + i + j * 65536];
#pragma unroll
        for (int j = 0; j < 4; j++) atomicAdd(&g_degs[idx[j] * CSTRIDE], 1);
    }
}
// shfl-based block scan (2 barriers instead of 20)
__global__ void prefix_kernel(const float* __restrict__ bsrc, const float* __restrict__ btgt) {
    __shared__ int smw[32];
    int t = threadIdx.x;
    int lane = t & 31, wrp = t >> 5;
    if (t < Hh) g_bsum[t] = bsrc[t] + btgt[t];
    int b = t * 4;
    int d0 = g_degs[(b + 0) * CSTRIDE];
    int d1 = g_degs[(b + 1) * CSTRIDE];
    int d2 = g_degs[(b + 2) * CSTRIDE];
    int d3 = g_degs[(b + 3) * CSTRIDE];
    // re-zero for the next replay (graph-capture safe: deterministic)
    g_degs[(b + 0) * CSTRIDE] = 0;
    g_degs[(b + 1) * CSTRIDE] = 0;
    g_degs[(b + 2) * CSTRIDE] = 0;
    g_degs[(b + 3) * CSTRIDE] = 0;
    int tot = d0 + d1 + d2 + d3;
    // warp inclusive scan
    int incl = tot;
#pragma unroll
    for (int off = 1; off < 32; off <<= 1) {
        int v = __shfl_up_sync(0xffffffffu, incl, off);
        if (lane >= off) incl += v;
    }
    if (lane == 31) smw[wrp] = incl;
    __syncthreads();
    if (wrp == 0) {
        int wv = smw[lane];
        int wi = wv;
#pragma unroll
        for (int off = 1; off < 32; off <<= 1) {
            int v = __shfl_up_sync(0xffffffffu, wi, off);
            if (lane >= off) wi += v;
        }
        smw[lane] = wi - wv;  // exclusive warp offset
    }
    __syncthreads();
    int excl = (incl - tot) + smw[wrp];
    g_rowptr[b]     = excl; g_curs[(b + 0) * CSTRIDE] = excl; excl += d0;
    g_rowptr[b + 1] = excl; g_curs[(b + 1) * CSTRIDE] = excl; excl += d1;
    g_rowptr[b + 2] = excl; g_curs[(b + 2) * CSTRIDE] = excl; excl += d2;
    g_rowptr[b + 3] = excl; g_curs[(b + 3) * CSTRIDE] = excl; excl += d3;
    if (t == 1023) g_rowptr[Nn] = excl;
}
__global__ void fill_kernel(const int* __restrict__ ei) {
    int t = blockIdx.x * blockDim.x + threadIdx.x;
    int dst[4], src[4], pos[4];
#pragma unroll
    for (int i = 0; i < 4; i++) {
        dst[i] = ei[Ee + t + i * 65536];
        src[i] = ei[t + i * 65536];
    }
#pragma unroll
    for (int i = 0; i < 4; i++) pos[i] = atomicAdd(&g_curs[dst[i] * CSTRIDE], 1);
#pragma unroll
    for (int i = 0; i < 4; i++) g_col[pos[i]] = src[i];
}
// 2 warps per node (R12 config). Partials -> g_X1 / g_t. X2 no longer
// materialized: the agg GEMM stages h*rw directly.
__global__ void __launch_bounds__(256) aggsum_kernel() {
    int wrp = threadIdx.x >> 5;
    int n = blockIdx.x * 4 + (wrp >> 1);
    int half = wrp & 1;
    int lane = threadIdx.x & 31;
    int s0 = g_rowptr[n], s1 = g_rowptr[n + 1];
    int d = s1 - s0;
    float inv = 1.0f / (float)max(d, 1);
    float rwv = d > 0 ? 1.0f : 0.0f;
    const uint4* hb = (const uint4*)g_hbf;

    float a[8] = {};
    for (int e = s0 + half * 8; e + 8 <= s1; e += 16) {
        int cc[8];
#pragma unroll
        for (int j = 0; j < 8; j++) cc[j] = g_col[e + j];
        uint4 u[8];
#pragma unroll
        for (int j = 0; j < 8; j++) u[j] = hb[(size_t)cc[j] * 32 + lane];
#pragma unroll
        for (int j = 0; j < 8; j++) {
            a[0] += blo(u[j].x); a[1] += bhi(u[j].x);
            a[2] += blo(u[j].y); a[3] += bhi(u[j].y);
            a[4] += blo(u[j].z); a[5] += bhi(u[j].z);
            a[6] += blo(u[j].w); a[7] += bhi(u[j].w);
        }
    }
    if (half == 1) {
        for (int e = s1 - (d & 7); e < s1; e++) {
            uint4 u0 = hb[(size_t)g_col[e] * 32 + lane];
            a[0] += blo(u0.x); a[1] += bhi(u0.x);
            a[2] += blo(u0.y); a[3] += bhi(u0.y);
            a[4] += blo(u0.z); a[5] += bhi(u0.z);
            a[6] += blo(u0.w); a[7] += bhi(u0.w);
        }
    }
    float* x1 = (half ? g_t : g_X1) + (size_t)n * Hh + lane * 8;
    *(float4*)x1       = make_float4(a[0] * inv, a[1] * inv, a[2] * inv, a[3] * inv);
    *(float4*)(x1 + 4) = make_float4(a[4] * inv, a[5] * inv, a[6] * inv, a[7] * inv);
    if (half == 0 && lane == 0) g_rw[n] = rwv;
}

// ---------------- tf32 mma.sync GEMM (fp32 out) --------------------------------
// C = (A [+Acb elementwise]) @ B (+ A2[*rw row-scale]@B2) (+ bias*rowScale)
template <int ACT, int SCALEA2>
__global__ void __launch_bounds__(256) mm_gemm(
    const float* __restrict__ A, const float* __restrict__ Acb,
    const float* __restrict__ B,
    const float* __restrict__ A2, const float* __restrict__ B2,
    const float* __restrict__ bias, const float* __restrict__ rowScale,
    float* __restrict__ C, int K, int Nc)
{
    __shared__ __align__(16) float As[128 * 36];
    __shared__ __align__(16) float Bs[32 * 72];
    int tid = threadIdx.x, wid = tid >> 5, lane = tid & 31;
    int gid = lane >> 2, tg = lane & 3;
    int moff = (wid & 3) * 32, noff = (wid >> 2) * 32;
    int m0 = blockIdx.y * 128, n0 = blockIdx.x * 64;

    float c[2][4][4] = {};
    int steps1 = K / 32;
    int steps = A2 ? 2 * steps1 : steps1;

    float4 ra[4], rcb[4], rb[2];
    float rrw[4];
    {
#pragma unroll
        for (int i = 0; i < 4; i++) {
            int f = tid + i * 256, m = f >> 3, qq = f & 7;
            ra[i] = *(const float4*)(A + (size_t)(m0 + m) * K + qq * 4);
            if (Acb) rcb[i] = *(const float4*)(Acb + (size_t)(m0 + m) * K + qq * 4);
        }
#pragma unroll
        for (int i = 0; i < 2; i++) {
            int f = tid + i * 256, kk = f >> 4, qq = f & 15;
            rb[i] = *(const float4*)(B + (size_t)kk * Nc + n0 + qq * 4);
        }
    }

    for (int s = 0; s < steps; s++) {
        bool cmb = Acb && (s < steps1);
        bool sc2 = SCALEA2 && (s >= steps1);
        __syncthreads();
#pragma unroll
        for (int i = 0; i < 4; i++) {
            int f = tid + i * 256, m = f >> 3, qq = f & 7;
            float4 v = ra[i];
            if (cmb) {
                v.x += rcb[i].x; v.y += rcb[i].y;
                v.z += rcb[i].z; v.w += rcb[i].w;
            }
            if (sc2) {
                v.x *= rrw[i]; v.y *= rrw[i];
                v.z *= rrw[i]; v.w *= rrw[i];
            }
            *(float4*)&As[m * 36 + qq * 4] =
                make_float4(tf(v.x), tf(v.y), tf(v.z), tf(v.w));
        }
#pragma unroll
        for (int i = 0; i < 2; i++) {
            int f = tid + i * 256, kk = f >> 4, qq = f & 15;
            *(float4*)&Bs[kk * 72 + qq * 4] =
                make_float4(tf(rb[i].x), tf(rb[i].y), tf(rb[i].z), tf(rb[i].w));
        }
        __syncthreads();
        if (s + 1 < steps) {
            int s2 = s + 1;
            const float* Ag = (s2 < steps1) ? A : A2;
            const float* Bg = (s2 < steps1) ? B : B2;
            int k0 = ((s2 < steps1) ? s2 : (s2 - steps1)) * 32;
#pragma unroll
            for (int i = 0; i < 4; i++) {
                int f = tid + i * 256, m = f >> 3, qq = f & 7;
                ra[i] = *(const float4*)(Ag + (size_t)(m0 + m) * K + k0 + qq * 4);
                if (Acb && s2 < steps1)
                    rcb[i] = *(const float4*)(Acb + (size_t)(m0 + m) * K + k0 + qq * 4);
                if (SCALEA2 && s2 >= steps1) rrw[i] = g_rw[m0 + m];
            }
#pragma unroll
            for (int i = 0; i < 2; i++) {
                int f = tid + i * 256, kk = f >> 4, qq = f & 15;
                rb[i] = *(const float4*)(Bg + (size_t)(k0 + kk) * Nc + n0 + qq * 4);
            }
        }
#pragma unroll
        for (int ks = 0; ks < 4; ks++) {
            int ck = ks * 8 + tg;
            uint32_t a0[4], a1[4];
            a0[0] = __float_as_uint(As[(moff + gid) * 36 + ck]);
            a0[1] = __float_as_uint(As[(moff + gid + 8) * 36 + ck]);
            a0[2] = __float_as_uint(As[(moff + gid) * 36 + ck + 4]);
            a0[3] = __float_as_uint(As[(moff + gid + 8) * 36 + ck + 4]);
            a1[0] = __float_as_uint(As[(moff + 16 + gid) * 36 + ck]);
            a1[1] = __float_as_uint(As[(moff + 24 + gid) * 36 + ck]);
            a1[2] = __float_as_uint(As[(moff + 16 + gid) * 36 + ck + 4]);
            a1[3] = __float_as_uint(As[(moff + 24 + gid) * 36 + ck + 4]);
#pragma unroll
            for (int jn = 0; jn < 4; jn++) {
                uint32_t b0 = __float_as_uint(Bs[ck * 72 + noff + jn * 8 + gid]);
                uint32_t b1 = __float_as_uint(Bs[(ck + 4) * 72 + noff + jn * 8 + gid]);
                mma8(c[0][jn], a0, b0, b1);
                mma8(c[1][jn], a1, b0, b1);
            }
        }
    }

#pragma unroll
    for (int im = 0; im < 2; im++) {
        int r1 = m0 + moff + im * 16 + gid, r2 = r1 + 8;
        float rs1 = rowScale ? rowScale[r1] : 1.0f;
        float rs2 = rowScale ? rowScale[r2] : 1.0f;
#pragma unroll
        for (int jn = 0; jn < 4; jn++) {
            int col = n0 + noff + jn * 8 + 2 * tg;
            float v00 = c[im][jn][0], v01 = c[im][jn][1];
            float v10 = c[im][jn][2], v11 = c[im][jn][3];
            if (bias) {
                float bb0 = bias[col], bb1 = bias[col + 1];
                v00 += bb0 * rs1; v01 += bb1 * rs1;
                v10 += bb0 * rs2; v11 += bb1 * rs2;
            }
            if (ACT == 1) {
                v00 = gelu(v00); v01 = gelu(v01);
                v10 = gelu(v10); v11 = gelu(v11);
            }
            *(float2*)(C + (size_t)r1 * Nc + col) = make_float2(v00, v01);
            *(float2*)(C + (size_t)r2 * Nc + col) = make_float2(v10, v11);
        }
    }
}

// ---------------- tf32 GEMM with fused residual + layernorm (R12 32-row) -------
template <int KK, int COMBINE>
__global__ void __launch_bounds__(256) mm_gemm_ln(
    const float* __restrict__ A, const float* __restrict__ A2,
    const float* __restrict__ B,
    const float* __restrict__ bias, const float* __restrict__ res,
    const float* __restrict__ g, const float* __restrict__ be,
    float* __restrict__ C)
{
    __shared__ __align__(16) float As[32 * 36];
    __shared__ __align__(16) float Bs[32 * 264];
    __shared__ float redS[32 * 4], redQ[32 * 4];
    int tid = threadIdx.x, wid = tid >> 5, lane = tid & 31;
    int gid = lane >> 2, tg = lane & 3;
    int moff = (wid & 1) * 16, noff = (wid >> 1) * 64;
    int m0 = blockIdx.x * 32;
    const int steps = KK / 32;
    int am = tid >> 3, aq = tid & 7;

    float il[4];
    if (COMBINE) {
        int r = m0 + am;
#pragma unroll
        for (int hd = 0; hd < 4; hd++)
            il[hd] = 1.0f / (g_acc[hd * Nn + r] + g_acc[(NHEADS + hd) * Nn + r]);
    }

    float c[8][4] = {};
    float4 ra, ra2, rb[8];
    {
        ra = *(const float4*)(A + (size_t)(m0 + am) * KK + aq * 4);
        if (COMBINE) ra2 = *(const float4*)(A2 + (size_t)(m0 + am) * KK + aq * 4);
#pragma unroll
        for (int i = 0; i < 8; i++) {
            int f = tid + i * 256, kk = f >> 6, q2 = f & 63;
            rb[i] = *(const float4*)(B + (size_t)kk * Hh + q2 * 4);
        }
    }
    for (int s = 0; s < steps; s++) {
        __syncthreads();
        {
            float4 v = ra;
            if (COMBINE) {
                float sc = il[s >> 1];
                v = make_float4((ra.x + ra2.x) * sc, (ra.y + ra2.y) * sc,
                                (ra.z + ra2.z) * sc, (ra.w + ra2.w) * sc);
            }
            *(float4*)&As[am * 36 + aq * 4] =
                make_float4(tf(v.x), tf(v.y), tf(v.z), tf(v.w));
        }
#pragma unroll
        for (int i = 0; i < 8; i++) {
            int f = tid + i * 256, kk = f >> 6, q2 = f & 63;
            *(float4*)&Bs[kk * 264 + q2 * 4] =
                make_float4(tf(rb[i].x), tf(rb[i].y), tf(rb[i].z), tf(rb[i].w));
        }
        __syncthreads();
        if (s + 1 < steps) {
            int k0 = (s + 1) * 32;
            ra = *(const float4*)(A + (size_t)(m0 + am) * KK + k0 + aq * 4);
            if (COMBINE) ra2 = *(const float4*)(A2 + (size_t)(m0 + am) * KK + k0 + aq * 4);
#pragma unroll
            for (int i = 0; i < 8; i++) {
                int f = tid + i * 256, kk = f >> 6, q2 = f & 63;
                rb[i] = *(const float4*)(B + (size_t)(k0 + kk) * Hh + q2 * 4);
            }
        }
#pragma unroll
        for (int ks = 0; ks < 4; ks++) {
            int ck = ks * 8 + tg;
            uint32_t a0[4];
            a0[0] = __float_as_uint(As[(moff + gid) * 36 + ck]);
            a0[1] = __float_as_uint(As[(moff + gid + 8) * 36 + ck]);
            a0[2] = __float_as_uint(As[(moff + gid) * 36 + ck + 4]);
            a0[3] = __float_as_uint(As[(moff + gid + 8) * 36 + ck + 4]);
#pragma unroll
            for (int jn = 0; jn < 8; jn++) {
                uint32_t b0 = __float_as_uint(Bs[ck * 264 + noff + jn * 8 + gid]);
                uint32_t b1 = __float_as_uint(Bs[(ck + 4) * 264 + noff + jn * 8 + gid]);
                mma8(c[jn], a0, b0, b1);
            }
        }
    }

    int r1 = m0 + moff + gid, r2 = r1 + 8;
    float s1 = 0, q1 = 0, s2 = 0, q2 = 0;
#pragma unroll
    for (int jn = 0; jn < 8; jn++) {
        int col = noff + jn * 8 + 2 * tg;
        float2 rr1 = *(const float2*)(res + (size_t)r1 * Hh + col);
        float2 rr2 = *(const float2*)(res + (size_t)r2 * Hh + col);
        float bb0 = bias[col], bb1 = bias[col + 1];
        c[jn][0] += bb0 + rr1.x; c[jn][1] += bb1 + rr1.y;
        c[jn][2] += bb0 + rr2.x; c[jn][3] += bb1 + rr2.y;
        s1 += c[jn][0] + c[jn][1];
        q1 += c[jn][0] * c[jn][0] + c[jn][1] * c[jn][1];
        s2 += c[jn][2] + c[jn][3];
        q2 += c[jn][2] * c[jn][2] + c[jn][3] * c[jn][3];
    }
    s1 += __shfl_xor_sync(0xffffffffu, s1, 1); s1 += __shfl_xor_sync(0xffffffffu, s1, 2);
    q1 += __shfl_xor_sync(0xffffffffu, q1, 1); q1 += __shfl_xor_sync(0xffffffffu, q1, 2);
    s2 += __shfl_xor_sync(0xffffffffu, s2, 1); s2 += __shfl_xor_sync(0xffffffffu, s2, 2);
    q2 += __shfl_xor_sync(0xffffffffu, q2, 1); q2 += __shfl_xor_sync(0xffffffffu, q2, 2);
    if (tg == 0) {
        int cg = wid >> 1;
        redS[(moff + gid) * 4 + cg] = s1;
        redQ[(moff + gid) * 4 + cg] = q1;
        redS[(moff + gid + 8) * 4 + cg] = s2;
        redQ[(moff + gid + 8) * 4 + cg] = q2;
    }
    __syncthreads();
    int ri1 = (moff + gid) * 4, ri2 = (moff + gid + 8) * 4;
    float su1 = redS[ri1] + redS[ri1 + 1] + redS[ri1 + 2] + redS[ri1 + 3];
    float qu1 = redQ[ri1] + redQ[ri1 + 1] + redQ[ri1 + 2] + redQ[ri1 + 3];
    float su2 = redS[ri2] + redS[ri2 + 1] + redS[ri2 + 2] + redS[ri2 + 3];
    float qu2 = redQ[ri2] + redQ[ri2 + 1] + redQ[ri2 + 2] + redQ[ri2 + 3];
    float mu1 = su1 * (1.0f / Hh), mu2 = su2 * (1.0f / Hh);
    float rstd1 = rsqrtf(qu1 * (1.0f / Hh) - mu1 * mu1 + 1e-5f);
    float rstd2 = rsqrtf(qu2 * (1.0f / Hh) - mu2 * mu2 + 1e-5f);
#pragma unroll
    for (int jn = 0; jn < 8; jn++) {
        int col = noff + jn * 8 + 2 * tg;
        float g0 = g[col], g1v = g[col + 1];
        float e0 = be[col], e1 = be[col + 1];
        *(float2*)(C + (size_t)r1 * Hh + col) = make_float2(
            (c[jn][0] - mu1) * rstd1 * g0 + e0, (c[jn][1] - mu1) * rstd1 * g1v + e1);
        *(float2*)(C + (size_t)r2 * Hh + col) = make_float2(
            (c[jn][2] - mu2) * rstd2 * g0 + e0, (c[jn][3] - mu2) * rstd2 * g1v + e1);
    }
}

// ---------------- fused QKV projection (tf32 mma, bf16x2-packed out) -----------
__global__ void __launch_bounds__(256) qkv_gemm(
    const float* __restrict__ h, const float* __restrict__ agg,
    const float* __restrict__ Wq, const float* __restrict__ Wk,
    const float* __restrict__ Wv,
    const float* __restrict__ bq, const float* __restrict__ bk,
    const float* __restrict__ bv,
    uint32_t* __restrict__ qo, uint32_t* __restrict__ ko, uint32_t* __restrict__ vo)
{
    __shared__ __align__(16) float As[128 * 36];
    __shared__ __align__(16) float Bs[32 * 72];
    int z = blockIdx.z;
    const float* A    = (z == 0) ? h  : agg;
    const float* B    = (z == 0) ? Wq : (z == 1 ? Wk : Wv);
    const float* bias = (z == 0) ? bq : (z == 1 ? bk : bv);
    uint32_t*    C    = (z == 0) ? qo : (z == 1 ? ko : vo);
    float osc = (z == 0) ? QSC : 1.0f;

    int tid = threadIdx.x, wid = tid >> 5, lane = tid & 31;
    int gid = lane >> 2, tg = lane & 3;
    int moff = (wid & 3) * 32, noff = (wid >> 2) * 32;
    int m0 = blockIdx.y * 128, n0 = blockIdx.x * 64;

    float c[2][4][4] = {};
    float4 ra[4], rb[2];
#pragma unroll
    for (int i = 0; i < 4; i++) {
        int f = tid + i * 256, m = f >> 3, qq = f & 7;
        ra[i] = *(const float4*)(A + (size_t)(m0 + m) * Hh + qq * 4);
    }
#pragma unroll
    for (int i = 0; i < 2; i++) {
        int f = tid + i * 256, kk = f >> 4, qq = f & 15;
        rb[i] = *(const float4*)(B + (size_t)kk * Hh + n0 + qq * 4);
    }

#pragma unroll
    for (int s = 0; s < 8; s++) {
        __syncthreads();
#pragma unroll
        for (int i = 0; i < 4; i++) {
            int f = tid + i * 256, m = f >> 3, qq = f & 7;
            *(float4*)&As[m * 36 + qq * 4] =
                make_float4(tf(ra[i].x), tf(ra[i].y), tf(ra[i].z), tf(ra[i].w));
        }
#pragma unroll
        for (int i = 0; i < 2; i++) {
            int f = tid + i * 256, kk = f >> 4, qq = f & 15;
            *(float4*)&Bs[kk * 72 + qq * 4] =
                make_float4(tf(rb[i].x), tf(rb[i].y), tf(rb[i].z), tf(rb[i].w));
        }
        __syncthreads();
        if (s + 1 < 8) {
            int k0 = (s + 1) * 32;
#pragma unroll
            for (int i = 0; i < 4; i++) {
                int f = tid + i * 256, m = f >> 3, qq = f & 7;
                ra[i] = *(const float4*)(A + (size_t)(m0 + m) * Hh + k0 + qq * 4);
            }
#pragma unroll
            for (int i = 0; i < 2; i++) {
                int f = tid + i * 256, kk = f >> 4, qq = f & 15;
                rb[i] = *(const float4*)(B + (size_t)(k0 + kk) * Hh + n0 + qq * 4);
            }
        }
#pragma unroll
        for (int ks = 0; ks < 4; ks++) {
            int ck = ks * 8 + tg;
            uint32_t a0[4], a1[4];
            a0[0] = __float_as_uint(As[(moff + gid) * 36 + ck]);
            a0[1] = __float_as_uint(As[(moff + gid + 8) * 36 + ck]);
            a0[2] = __float_as_uint(As[(moff + gid) * 36 + ck + 4]);
            a0[3] = __float_as_uint(As[(moff + gid + 8) * 36 + ck + 4]);
            a1[0] = __float_as_uint(As[(moff + 16 + gid) * 36 + ck]);
            a1[1] = __float_as_uint(As[(moff + 24 + gid) * 36 + ck]);
            a1[2] = __float_as_uint(As[(moff + 16 + gid) * 36 + ck + 4]);
            a1[3] = __float_as_uint(As[(moff + 24 + gid) * 36 + ck + 4]);
#pragma unroll
            for (int jn = 0; jn < 4; jn++) {
                uint32_t b0 = __float_as_uint(Bs[ck * 72 + noff + jn * 8 + gid]);
                uint32_t b1 = __float_as_uint(Bs[(ck + 4) * 72 + noff + jn * 8 + gid]);
                mma8(c[0][jn], a0, b0, b1);
                mma8(c[1][jn], a1, b0, b1);
            }
        }
    }

#pragma unroll
    for (int im = 0; im < 2; im++) {
        int r1 = m0 + moff + im * 16 + gid, r2 = r1 + 8;
#pragma unroll
        for (int jn = 0; jn < 4; jn++) {
            int col = n0 + noff + jn * 8 + 2 * tg;
            float bb0 = bias[col], bb1 = bias[col + 1];
            C[(size_t)r1 * (Hh / 2) + (col >> 1)] =
                bf2((c[im][jn][0] + bb0) * osc, (c[im][jn][1] + bb1) * osc);
            C[(size_t)r2 * (Hh / 2) + (col >> 1)] =
                bf2((c[im][jn][2] + bb0) * osc, (c[im][jn][3] + bb1) * osc);
        }
    }
}

// ---------------- flash attention (bf16 mma, split-K over 2 halves) ------------
#define AP 36
#define ATILE (64 * AP)
#define NBUF 4
#define ATT_SMEM (NBUF * 2 * ATILE * 4)
#define NT_HALF (Nn / 128)  // 32 tiles per half
__device__ __forceinline__ void attn_issue(uint32_t sbase, int buf,
                                           const uint32_t* kbf, const uint32_t* vbf,
                                           int t, int hd, int tid) {
    uint32_t Kb = sbase + (uint32_t)buf * (2 * ATILE * 4);
    uint32_t Vb = Kb + ATILE * 4;
#pragma unroll
    for (int i = 0; i < 2; i++) {
        int f = tid + i * 256, r = f >> 3, ch = f & 7;
        const uint32_t* kg = kbf + (size_t)(t * 64 + r) * 128 + hd * 32 + ch * 4;
        const uint32_t* vg = vbf + (size_t)(t * 64 + r) * 128 + hd * 32 + ch * 4;
        uint32_t so = (uint32_t)(r * AP + ch * 4) * 4u;
        CPA16(Kb + so, kg);
        CPA16(Vb + so, vg);
    }
}

__global__ void __launch_bounds__(256) attn_kernel(
    const uint32_t* __restrict__ qbf, const uint32_t* __restrict__ kbf,
    const uint32_t* __restrict__ vbf,
    float* __restrict__ o0, float* __restrict__ o1)
{
    extern __shared__ __align__(16) uint32_t smt[];
    uint32_t sbase = smem_u32(smt);
    int tid = threadIdx.x, wid = tid >> 5, lane = tid & 31;
    int gid = lane >> 2, tg = lane & 3;
    int l8 = lane >> 3, lr = lane & 7;
    int hd = blockIdx.y;
    int z = blockIdx.z;
    int q0 = blockIdx.x * 128;
    int wrow = wid * 16;
    int t0 = z * NT_HALF;

    uint32_t koff = (uint32_t)(((l8 >> 1) * 8 + lr) * AP + (l8 & 1) * 4) * 4u;
    uint32_t voff = (uint32_t)((l8 * 8 + lr) * AP) * 4u;

    uint32_t qa[4][4];
    {
        const uint32_t* q1 = qbf + (size_t)(q0 + wrow + gid) * 128 + hd * 32;
        const uint32_t* q2 = q1 + 8 * 128;
#pragma unroll
        for (int ks = 0; ks < 4; ks++) {
            qa[ks][0] = q1[ks * 8 + tg];
            qa[ks][1] = q2[ks * 8 + tg];
            qa[ks][2] = q1[ks * 8 + tg + 4];
            qa[ks][3] = q2[ks * 8 + tg + 4];
        }
    }

    attn_issue(sbase, 0, kbf, vbf, t0, hd, tid); CP_COMMIT();
    attn_issue(sbase, 1, kbf, vbf, t0 + 1, hd, tid); CP_COMMIT();

    float o[8][4] = {};
    float acc0 = 0.0f, acc1 = 0.0f;

    for (int ti = 0; ti < NT_HALF; ti++) {
        if (ti + 2 < NT_HALF) {
            attn_issue(sbase, (ti + 2) & (NBUF - 1), kbf, vbf, t0 + ti + 2, hd, tid);
            CP_COMMIT();
            CP_WAIT(2);
        } else if (ti + 1 < NT_HALF) {
            CP_WAIT(1);
        } else {
            CP_WAIT(0);
        }
        __syncthreads();
        uint32_t Kb = sbase + (uint32_t)(ti & (NBUF - 1)) * (2 * ATILE * 4);
        uint32_t Vb = Kb + ATILE * 4;

        // S = Q @ K^T
        float s[8][4] = {};
#pragma unroll
        for (int kb = 0; kb < 4; kb++) {
#pragma unroll
            for (int jnp = 0; jnp < 4; jnp++) {
                uint32_t b0, b1, b2, b3;
                uint32_t addr = Kb + koff + (uint32_t)(jnp * 16 * AP + kb * 8) * 4u;
                ldsm4(b0, b1, b2, b3, addr);
                mmabf(s[2 * jnp],     qa[kb], b0, b1);
                mmabf(s[2 * jnp + 1], qa[kb], b2, b3);
            }
        }

        // no-max softmax
        uint32_t pa[4][4];
#pragma unroll
        for (int jn = 0; jn < 8; jn++) {
            s[jn][0] = ex2(s[jn][0]);
            s[jn][1] = ex2(s[jn][1]);
            s[jn][2] = ex2(s[jn][2]);
            s[jn][3] = ex2(s[jn][3]);
            acc0 += s[jn][0] + s[jn][1];
            acc1 += s[jn][2] + s[jn][3];
        }
#pragma unroll
        for (int ks = 0; ks < 4; ks++) {
            pa[ks][0] = bf2(s[2 * ks][0], s[2 * ks][1]);
            pa[ks][1] = bf2(s[2 * ks][2], s[2 * ks][3]);
            pa[ks][2] = bf2(s[2 * ks + 1][0], s[2 * ks + 1][1]);
            pa[ks][3] = bf2(s[2 * ks + 1][2], s[2 * ks + 1][3]);
        }

        // O += P @ V
#pragma unroll
        for (int jn = 0; jn < 8; jn++) {
#pragma unroll
            for (int ksp = 0; ksp < 2; ksp++) {
                uint32_t b0, b1, b2, b3;
                uint32_t addr = Vb + voff + (uint32_t)(ksp * 32 * AP + jn * 4) * 4u;
                ldsm4t(b0, b1, b2, b3, addr);
                mmabf(o[jn], pa[2 * ksp],     b0, b1);
                mmabf(o[jn], pa[2 * ksp + 1], b2, b3);
            }
        }
    }

    // partial epilogue: row sums + unnormalized O
    acc0 += __shfl_xor_sync(0xffffffffu, acc0, 1);
    acc0 += __shfl_xor_sync(0xffffffffu, acc0, 2);
    acc1 += __shfl_xor_sync(0xffffffffu, acc1, 1);
    acc1 += __shfl_xor_sync(0xffffffffu, acc1, 2);
    float* od = z ? o1 : o0;
    int r1 = q0 + wrow + gid, r2 = r1 + 8;
    if (tg == 0) {
        g_acc[(z * NHEADS + hd) * Nn + r1] = acc0;
        g_acc[(z * NHEADS + hd) * Nn + r2] = acc1;
    }
#pragma unroll
    for (int jn = 0; jn < 8; jn++) {
        int col = hd * DHd + jn * 8 + 2 * tg;
        *(float2*)(od + (size_t)r1 * Hh + col) = make_float2(o[jn][0], o[jn][1]);
        *(float2*)(od + (size_t)r2 * Hh + col) = make_float2(o[jn][2], o[jn][3]);
    }
}

// ---------------- launch ------------------------------------------------------
extern "C" void kernel_launch(void* const* d_in, const int* in_sizes, int n_in,
                              void* d_out, int out_size)
{
    const float* h     = (const float*)d_in[0];
    const int*   ei    = (const int*)d_in[1];
    const float* W_src = (const float*)d_in[2];
    const float* b_src = (const float*)d_in[3];
    const float* W_tgt = (const float*)d_in[4];
    const float* b_tgt = (const float*)d_in[5];
    const float* Wq = (const float*)d_in[6];  const float* bq = (const float*)d_in[7];
    const float* Wk = (const float*)d_in[8];  const float* bk = (const float*)d_in[9];
    const float* Wv = (const float*)d_in[10]; const float* bv = (const float*)d_in[11];
    const float* Wo = (const float*)d_in[12]; const float* bo = (const float*)d_in[13];
    const float* W1 = (const float*)d_in[14]; const float* b1 = (const float*)d_in[15];
    const float* W2 = (const float*)d_in[16]; const float* b2 = (const float*)d_in[17];
    const float* g1 = (const float*)d_in[18]; const float* be1 = (const float*)d_in[19];
    const float* g2 = (const float*)d_in[20]; const float* be2 = (const float*)d_in[21];
    float* out = (float*)d_out;

    float *pX1, *pX2, *pagg, *pq, *pk, *pv, *px, *pt, *pbsum, *prw;
    cudaGetSymbolAddress((void**)&pX1,  g_X1);
    cudaGetSymbolAddress((void**)&pX2,  g_X2);
    cudaGetSymbolAddress((void**)&pagg, g_agg);
    cudaGetSymbolAddress((void**)&pq,   g_q);
    cudaGetSymbolAddress((void**)&pk,   g_k);
    cudaGetSymbolAddress((void**)&pv,   g_v);
    cudaGetSymbolAddress((void**)&px,   g_x);
    cudaGetSymbolAddress((void**)&pt,   g_t);
    cudaGetSymbolAddress((void**)&pbsum, g_bsum);
    cudaGetSymbolAddress((void**)&prw,  g_rw);

    // graph preprocessing (R12 config; shfl prefix scan)
    pack_deg_kernel<<<Nn * 128 / 256, 256>>>(h, ei);
    prefix_kernel<<<1, 1024>>>(b_src, b_tgt);
    fill_kernel<<<256, 256>>>(ei);
    aggsum_kernel<<<Nn / 4, 256>>>();   // 2 warps/node; partials in X1 + t

    dim3 gH(Hh / 64, Nn / 128);
    // agg = (X1a + X1b)@W_src + (h*rw)@W_tgt + rw*(b_src+b_tgt)
    // (X2 never materialized: rw row-scale applied at A2 tile staging)
    mm_gemm<0, 1><<<gH, 256>>>(pX1, pt, W_src, h, W_tgt, pbsum, prw, pagg, Hh, Hh);

    // fused q/k/v projections -> bf16x2-packed (q pre-scaled)
    qkv_gemm<<<dim3(Hh / 64, Nn / 128, 3), 256>>>(
        h, pagg, Wq, Wk, Wv, bq, bk, bv,
        (uint32_t*)pq, (uint32_t*)pk, (uint32_t*)pv);

    // flash attention: split-K over 2 halves (X1/X2 reused as O partials)
    cudaFuncSetAttribute(attn_kernel, cudaFuncAttributeMaxDynamicSharedMemorySize, ATT_SMEM);
    attn_kernel<<<dim3(Nn / 128, NHEADS, 2), 256, ATT_SMEM>>>(
        (const uint32_t*)pq, (const uint32_t*)pk, (const uint32_t*)pv, pX1, pX2);

    // x = LN(h + ((O0+O1)*il)@Wo + bo)  -- combine fused (R12 32-row tiles)
    mm_gemm_ln<256, 1><<<Nn / 32, 256>>>(pX1, pX2, Wo, bo, h, g1, be1, px);

    // FFN: t = gelu(x@W1 + b1) ; out = LN(x + t@W2 + b2)
    mm_gemm<1, 0><<<dim3(2 * Hh / 64, Nn / 128), 256>>>(
        px, nullptr, W1, nullptr, nullptr, b1, nullptr, pt, Hh, 2 * Hh);
    mm_gemm_ln<512, 0><<<Nn / 32, 256>>>(pt, nullptr, W2, b2, px, g2, be2, out);

    (void)in_sizes; (void)n_in; (void)out_size;
}